// round 8
// baseline (speedup 1.0000x reference)
#include <cuda_runtime.h>
#include <cstdint>
#include <cstddef>

#define NNODES   50000
#define EDGESMAX 800000
#define HDIM     256   // NUM_HEADS * OUT_DIM
#define NBLK     391   // ceil(NNODES / 128)

// -------- scratch (static __device__ arrays; no allocation allowed) --------
__device__ float    g_Q[(size_t)NNODES * HDIM];
__device__ float    g_K[(size_t)NNODES * HDIM];
__device__ float    g_V[(size_t)NNODES * HDIM];
__device__ int      g_deg[NNODES];        // zero-init at load; scan re-zeroes it
__device__ int      g_cursor[NNODES];
__device__ int      g_rowptr[NNODES + 1];
__device__ int      g_csr_src[EDGESMAX];
// pre-converted tf32 operands in fragment-major layout:
__device__ uint32_t g_hfrag[(size_t)NBLK * 8 * 4096];   // [bm][stage][4096]
__device__ uint32_t g_wfrag[(size_t)6 * 8 * 4096];      // [bn][stage][4096]

__device__ __forceinline__ uint32_t f2tf32(float x) {
    uint32_t r;
    asm("cvt.rna.tf32.f32 %0, %1;" : "=r"(r) : "f"(x));
    return r;
}

__device__ __forceinline__ void cp_async16(uint32_t saddr, const void* gptr) {
    asm volatile("cp.async.cg.shared.global [%0], [%1], 16;"
                 :: "r"(saddr), "l"(gptr));
}

// ---------------------------------------------------------------------------
// CSR build: histogram -> exclusive scan (seeds cursor, re-zeroes deg) -> scatter
// ---------------------------------------------------------------------------
__global__ void hist_kernel(const int* __restrict__ dst, int E) {
    int e = blockIdx.x * blockDim.x + threadIdx.x;
    if (e < E) atomicAdd(&g_deg[dst[e]], 1);
}

__global__ __launch_bounds__(1024) void scan_kernel(int n) {
    __shared__ int warp_sums[32];
    __shared__ int s_carry;
    const int tid  = threadIdx.x;
    const int lane = tid & 31;
    const int wid  = tid >> 5;
    if (tid == 0) s_carry = 0;
    __syncthreads();

    for (int base = 0; base < n; base += 1024) {
        int i = base + tid;
        int v = (i < n) ? g_deg[i] : 0;
        int x = v;
        #pragma unroll
        for (int off = 1; off < 32; off <<= 1) {
            int t = __shfl_up_sync(0xffffffffu, x, off);
            if (lane >= off) x += t;
        }
        if (lane == 31) warp_sums[wid] = x;
        __syncthreads();
        if (wid == 0) {
            int w = warp_sums[lane];
            #pragma unroll
            for (int off = 1; off < 32; off <<= 1) {
                int t = __shfl_up_sync(0xffffffffu, w, off);
                if (lane >= off) w += t;
            }
            warp_sums[lane] = w;
        }
        __syncthreads();
        int warp_off = (wid > 0) ? warp_sums[wid - 1] : 0;
        int excl = s_carry + x + warp_off - v;
        if (i < n) {
            g_rowptr[i] = excl;
            g_cursor[i] = excl;
            g_deg[i]    = 0;
        }
        __syncthreads();
        if (tid == 1023) s_carry += warp_sums[31];
        __syncthreads();
    }
    if (tid == 0) g_rowptr[n] = s_carry;
}

__global__ void scatter_kernel(const int* __restrict__ src,
                               const int* __restrict__ dst, int E) {
    int e = blockIdx.x * blockDim.x + threadIdx.x;
    if (e < E) {
        int pos = atomicAdd(&g_cursor[dst[e]], 1);
        g_csr_src[pos] = src[e];
    }
}

// ---------------------------------------------------------------------------
// Pre-conversion to tf32 in fragment-major layout.
// A-frag index within a 128x32 stage tile (4096 u32):
//   ks*1024 + tile16*128 + u*16 + kk*4 + pos
//   where rr = tile16*16 + u + (pos&1)*8,  cc = ks*8 + kk + (pos>>1)*4
// B-frag index: ks*1024 + n*8 + kk*2 + posb,  cc = ks*8 + kk + posb*4
// ---------------------------------------------------------------------------
__global__ __launch_bounds__(256) void conv_h(const float* __restrict__ h, int Nrows) {
    __shared__ float tile[128 * 32];
    const int bm = blockIdx.x, st = blockIdx.y;
    const int t = threadIdx.x;
    #pragma unroll
    for (int j = 0; j < 16; j++) {
        int idx = t + j * 256;                    // 0..4095
        int rr = idx >> 5, cc = idx & 31;
        int grow = bm * 128 + rr;
        tile[idx] = (grow < Nrows) ? h[(size_t)grow * 256 + st * 32 + cc] : 0.0f;
    }
    __syncthreads();
    uint32_t* outp = g_hfrag + ((size_t)bm * 8 + st) * 4096;
    #pragma unroll
    for (int j = 0; j < 16; j++) {
        int o = t + j * 256;
        int ks = o >> 10, rem = o & 1023;
        int t16 = rem >> 7, rem2 = rem & 127;
        int u = rem2 >> 4, rem3 = rem2 & 15;
        int kk = rem3 >> 2, pos = rem3 & 3;
        int rr = t16 * 16 + u + (pos & 1) * 8;
        int cc = ks * 8 + kk + (pos >> 1) * 4;
        outp[o] = f2tf32(tile[rr * 32 + cc]);
    }
}

__global__ __launch_bounds__(256) void conv_w(
    const float* __restrict__ Wq, const float* __restrict__ Wk,
    const float* __restrict__ Wv)
{
    __shared__ float tile[128 * 32];
    const int bn = blockIdx.x, st = blockIdx.y;
    const int t = threadIdx.x;
    const float* W = (bn < 2) ? Wq : (bn < 4) ? Wk : Wv;
    const int ncol0 = (bn & 1) * 128;
    #pragma unroll
    for (int j = 0; j < 16; j++) {
        int idx = t + j * 256;
        int n = idx >> 5, cc = idx & 31;
        tile[idx] = W[(size_t)(ncol0 + n) * 256 + st * 32 + cc];
    }
    __syncthreads();
    uint32_t* outp = g_wfrag + ((size_t)bn * 8 + st) * 4096;
    #pragma unroll
    for (int j = 0; j < 16; j++) {
        int o = t + j * 256;
        int ks = o >> 10, rem = o & 1023;
        int n = rem >> 3, rem2 = rem & 7;
        int kk = rem2 >> 1, posb = rem2 & 1;
        int cc = ks * 8 + kk + posb * 4;
        outp[o] = f2tf32(tile[n * 32 + cc]);
    }
}

// ---------------------------------------------------------------------------
// Kernel 1: QKV projection from pre-formatted tf32 fragments.
// cp.async double-buffered; consumer: 4x LDS.128 + 4x LDS.64 + 16 MMA per ks.
// ---------------------------------------------------------------------------
#define GSMEM_BYTES (4 * 4096 * 4)     // A0|A1|B0|B1

__global__ __launch_bounds__(256, 2) void qkv_gemm(
    const float* __restrict__ bq, const float* __restrict__ bk,
    const float* __restrict__ bv, int Nrows)
{
    extern __shared__ uint32_t sm[];   // [A0|A1|B0|B1] each 4096 u32

    const int tid  = threadIdx.x;
    const int lane = tid & 31;
    const int warp = tid >> 5;
    const int wm = warp >> 2;          // 0..1
    const int wn = warp & 3;           // 0..3
    const int bm = blockIdx.x;
    const int bn = blockIdx.y;

    const float* bias;  float* target;
    if (bn < 2)      { bias = bq; target = g_Q; }
    else if (bn < 4) { bias = bk; target = g_K; }
    else             { bias = bv; target = g_V; }
    const int ncol0 = (bn & 1) * 128;

    const uint32_t* gA = g_hfrag + (size_t)bm * 8 * 4096;
    const uint32_t* gB = g_wfrag + (size_t)bn * 8 * 4096;
    const uint32_t smem_base = (uint32_t)__cvta_generic_to_shared(sm);

    float acc[4][4][4];
    #pragma unroll
    for (int i = 0; i < 4; i++)
        #pragma unroll
        for (int j = 0; j < 4; j++)
            #pragma unroll
            for (int k = 0; k < 4; k++) acc[i][j][k] = 0.0f;

    auto load_stage = [&](int s, int buf) {
        #pragma unroll
        for (int i = 0; i < 4; i++) {
            int e = (tid + i * 256) * 4;           // element offset of 16B chunk
            cp_async16(smem_base + (uint32_t)((buf * 4096 + e) * 4),
                       gA + (size_t)s * 4096 + e);
            cp_async16(smem_base + (uint32_t)(((2 + buf) * 4096 + e) * 4),
                       gB + (size_t)s * 4096 + e);
        }
        asm volatile("cp.async.commit_group;" ::: "memory");
    };

    load_stage(0, 0);

    for (int it = 0; it < 8; it++) {
        const int p = it & 1;
        if (it + 1 < 8) {
            load_stage(it + 1, 1 - p);
            asm volatile("cp.async.wait_group 1;" ::: "memory");
        } else {
            asm volatile("cp.async.wait_group 0;" ::: "memory");
        }
        __syncthreads();

        const uint32_t* A = sm + p * 4096;
        const uint32_t* B = sm + (2 + p) * 4096;

        #pragma unroll
        for (int ks = 0; ks < 4; ks++) {
            uint4 av[4];
            uint2 bv2[4];
            #pragma unroll
            for (int mt = 0; mt < 4; mt++)
                av[mt] = *(const uint4*)(A + ks * 1024 + (wm * 4 + mt) * 128
                                           + (lane >> 2) * 16 + (lane & 3) * 4);
            #pragma unroll
            for (int nt = 0; nt < 4; nt++)
                bv2[nt] = *(const uint2*)(B + ks * 1024
                                            + (wn * 32 + nt * 8 + (lane >> 2)) * 8
                                            + (lane & 3) * 2);
            #pragma unroll
            for (int mt = 0; mt < 4; mt++)
                #pragma unroll
                for (int nt = 0; nt < 4; nt++)
                    asm volatile(
                        "mma.sync.aligned.m16n8k8.row.col.f32.tf32.tf32.f32 "
                        "{%0,%1,%2,%3}, {%4,%5,%6,%7}, {%8,%9}, {%0,%1,%2,%3};"
                        : "+f"(acc[mt][nt][0]), "+f"(acc[mt][nt][1]),
                          "+f"(acc[mt][nt][2]), "+f"(acc[mt][nt][3])
                        : "r"(av[mt].x), "r"(av[mt].y), "r"(av[mt].z), "r"(av[mt].w),
                          "r"(bv2[nt].x), "r"(bv2[nt].y));
        }
        __syncthreads();
    }

    // epilogue: add bias, store
    #pragma unroll
    for (int mt = 0; mt < 4; mt++) {
        int r0 = wm * 64 + mt * 16 + (lane >> 2);
        #pragma unroll
        for (int nt = 0; nt < 4; nt++) {
            int c0 = wn * 32 + nt * 8 + (lane & 3) * 2;
            #pragma unroll
            for (int cc = 0; cc < 4; cc++) {
                int r = r0 + ((cc >= 2) ? 8 : 0);
                int c = c0 + (cc & 1);
                int grow = bm * 128 + r;
                if (grow < Nrows) {
                    int j = ncol0 + c;
                    target[(size_t)grow * 256 + j] = acc[mt][nt][cc] + bias[j];
                }
            }
        }
    }
}

// ---------------------------------------------------------------------------
// Kernel 2: single-pass fused attention.  One warp per destination node.
// ---------------------------------------------------------------------------
__global__ __launch_bounds__(256) void attn_fused(
    float* __restrict__ out, int n_nodes)
{
    const int node = (blockIdx.x * blockDim.x + threadIdx.x) >> 5;
    if (node >= n_nodes) return;
    const int lane = threadIdx.x & 31;
    const unsigned FULL = 0xffffffffu;
    const float inv = 0.17677669529663687f;   // 1/sqrt(32)

    const int beg = g_rowptr[node];
    const int end = g_rowptr[node + 1];

    const float4* Qr = (const float4*)(g_Q + (size_t)node * 256);
    const float4 q0 = Qr[lane];
    const float4 q1 = Qr[lane + 32];

    float4 acc0 = make_float4(0.f, 0.f, 0.f, 0.f);
    float4 acc1 = make_float4(0.f, 0.f, 0.f, 0.f);
    float z0 = 0.0f, z1 = 0.0f;

    for (int i = beg; i < end; i++) {
        const int s = g_csr_src[i];
        const float4* Kr = (const float4*)(g_K + (size_t)s * 256);
        const float4* Vr = (const float4*)(g_V + (size_t)s * 256);
        float4 k0 = Kr[lane];
        float4 k1 = Kr[lane + 32];
        float4 v0 = Vr[lane];
        float4 v1 = Vr[lane + 32];

        float p0 = k0.x * q0.x + k0.y * q0.y + k0.z * q0.z + k0.w * q0.w;
        float p1 = k1.x * q1.x + k1.y * q1.y + k1.z * q1.z + k1.w * q1.w;
        #pragma unroll
        for (int off = 4; off; off >>= 1) {
            p0 += __shfl_xor_sync(FULL, p0, off);
            p1 += __shfl_xor_sync(FULL, p1, off);
        }
        float sc0 = __expf(fminf(fmaxf(p0 * inv, -5.0f), 5.0f));
        float sc1 = __expf(fminf(fmaxf(p1 * inv, -5.0f), 5.0f));
        z0 += sc0;
        z1 += sc1;

        acc0.x += sc0 * v0.x; acc0.y += sc0 * v0.y;
        acc0.z += sc0 * v0.z; acc0.w += sc0 * v0.w;
        acc1.x += sc1 * v1.x; acc1.y += sc1 * v1.y;
        acc1.z += sc1 * v1.z; acc1.w += sc1 * v1.w;
    }

    const float rz0 = (z0 > 0.0f) ? 1.0f / z0 : 0.0f;
    const float rz1 = (z1 > 0.0f) ? 1.0f / z1 : 0.0f;
    acc0.x *= rz0; acc0.y *= rz0; acc0.z *= rz0; acc0.w *= rz0;
    acc1.x *= rz1; acc1.y *= rz1; acc1.z *= rz1; acc1.w *= rz1;

    float4* o = (float4*)(out + (size_t)node * 256);
    o[lane]      = acc0;
    o[lane + 32] = acc1;
}

// ---------------------------------------------------------------------------
extern "C" void kernel_launch(void* const* d_in, const int* in_sizes, int n_in,
                              void* d_out, int out_size)
{
    const float* h  = (const float*)d_in[0];
    const float* Wq = (const float*)d_in[1];
    const float* bq = (const float*)d_in[2];
    const float* Wk = (const float*)d_in[3];
    const float* bk = (const float*)d_in[4];
    const float* Wv = (const float*)d_in[5];
    const float* bv = (const float*)d_in[6];
    const int*   src = (const int*)d_in[7];
    const int*   dst = (const int*)d_in[8];
    float* out = (float*)d_out;

    const int N = in_sizes[0] / 256;   // 50000
    const int E = in_sizes[7];         // 800000
    const int nblk = (N + 127) / 128;  // 391

    // pre-convert operands to tf32 fragment-major layout
    conv_w<<<dim3(6, 8), 256>>>(Wq, Wk, Wv);
    conv_h<<<dim3(nblk, 8), 256>>>(h, N);

    // CSR build
    hist_kernel   <<<(E + 255) / 256, 256>>>(dst, E);
    scan_kernel   <<<1, 1024>>>(N);
    scatter_kernel<<<(E + 255) / 256, 256>>>(src, dst, E);

    // QKV projections: pipelined TF32 GEMM on pre-formatted fragments
    cudaFuncSetAttribute(qkv_gemm, cudaFuncAttributeMaxDynamicSharedMemorySize,
                         GSMEM_BYTES);
    dim3 grid(nblk, 6);
    qkv_gemm<<<grid, 256, GSMEM_BYTES>>>(bq, bk, bv, N);

    attn_fused<<<(N * 32 + 255) / 256, 256>>>(out, N);
}

// round 9
// speedup vs baseline: 1.4535x; 1.4535x over previous
#include <cuda_runtime.h>
#include <cstdint>
#include <cstddef>

#define NNODES   50000
#define EDGESMAX 800000
#define HDIM     256   // NUM_HEADS * OUT_DIM
#define SCAN_CHUNK 1024
#define NB_SCAN  ((NNODES + SCAN_CHUNK - 1) / SCAN_CHUNK)   // 49

// -------- scratch (static __device__ arrays; no allocation allowed) --------
__device__ float g_Q[(size_t)NNODES * HDIM];
__device__ float g_K[(size_t)NNODES * HDIM];
__device__ float g_V[(size_t)NNODES * HDIM];
__device__ int   g_deg[NNODES];        // zero-init at load; scan_final re-zeroes
__device__ int   g_cursor[NNODES];
__device__ int   g_rowptr[NNODES + 1];
__device__ int   g_csr_src[EDGESMAX];
__device__ int   g_bsum[NB_SCAN];
__device__ int   g_boff[NB_SCAN];

__device__ __forceinline__ uint32_t f2tf32(float x) {
    uint32_t r;
    asm("cvt.rna.tf32.f32 %0, %1;" : "=r"(r) : "f"(x));
    return r;
}

__device__ __forceinline__ void cp_async16(uint32_t saddr, const void* gptr, int src_bytes) {
    asm volatile("cp.async.cg.shared.global [%0], [%1], 16, %2;"
                 :: "r"(saddr), "l"(gptr), "r"(src_bytes));
}

// ---------------------------------------------------------------------------
// CSR build: histogram -> 3-phase scan -> scatter
// ---------------------------------------------------------------------------
__global__ void hist_kernel(const int* __restrict__ dst, int E) {
    int e = blockIdx.x * blockDim.x + threadIdx.x;
    if (e < E) atomicAdd(&g_deg[dst[e]], 1);
}

// phase 1: per-block exclusive scan of a 1024 chunk; block total to g_bsum
__global__ __launch_bounds__(1024) void scan_part(int n) {
    __shared__ int warp_sums[32];
    const int tid  = threadIdx.x;
    const int lane = tid & 31;
    const int wid  = tid >> 5;
    const int i = blockIdx.x * SCAN_CHUNK + tid;

    int v = (i < n) ? g_deg[i] : 0;
    int x = v;
    #pragma unroll
    for (int off = 1; off < 32; off <<= 1) {
        int t = __shfl_up_sync(0xffffffffu, x, off);
        if (lane >= off) x += t;
    }
    if (lane == 31) warp_sums[wid] = x;
    __syncthreads();
    if (wid == 0) {
        int w = warp_sums[lane];
        #pragma unroll
        for (int off = 1; off < 32; off <<= 1) {
            int t = __shfl_up_sync(0xffffffffu, w, off);
            if (lane >= off) w += t;
        }
        warp_sums[lane] = w;
    }
    __syncthreads();
    int warp_off = (wid > 0) ? warp_sums[wid - 1] : 0;
    if (i < n) g_rowptr[i] = x + warp_off - v;       // local exclusive
    if (tid == 1023) g_bsum[blockIdx.x] = x + warp_off;
}

// phase 2: single small block scans block sums -> exclusive offsets + total
__global__ __launch_bounds__(64) void scan_top(int nb, int n) {
    __shared__ int warp_sums[2];
    const int tid  = threadIdx.x;
    const int lane = tid & 31;
    const int wid  = tid >> 5;
    int v = (tid < nb) ? g_bsum[tid] : 0;
    int x = v;
    #pragma unroll
    for (int off = 1; off < 32; off <<= 1) {
        int t = __shfl_up_sync(0xffffffffu, x, off);
        if (lane >= off) x += t;
    }
    if (lane == 31) warp_sums[wid] = x;
    __syncthreads();
    int carry = (wid == 1) ? warp_sums[0] : 0;
    if (tid < nb) g_boff[tid] = x + carry - v;       // exclusive
    if (tid == nb - 1) g_rowptr[n] = x + carry;      // grand total
}

// phase 3: add offsets, seed cursor, restore deg invariant
__global__ void scan_final(int n) {
    int i = blockIdx.x * blockDim.x + threadIdx.x;
    if (i < n) {
        int r = g_rowptr[i] + g_boff[i >> 10];
        g_rowptr[i] = r;
        g_cursor[i] = r;
        g_deg[i]    = 0;
    }
}

__global__ void scatter_kernel(const int* __restrict__ src,
                               const int* __restrict__ dst, int E) {
    int e = blockIdx.x * blockDim.x + threadIdx.x;
    if (e < E) {
        int pos = atomicAdd(&g_cursor[dst[e]], 1);
        g_csr_src[pos] = src[e];
    }
}

// ---------------------------------------------------------------------------
// Kernel 1: fused QKV projection, 2-stage cp.async pipelined TF32 GEMM.
// (R6 version — best measured.)  Block tile 128x128x32, warp tile 64x32.
// ---------------------------------------------------------------------------
#define GSTAGE 4608          // 128 * 36 words per tile buffer
#define GSMEM_BYTES (4 * GSTAGE * 4)   // As[2] + Bs[2]

__global__ __launch_bounds__(256) void qkv_gemm(
    const float* __restrict__ h,
    const float* __restrict__ Wq, const float* __restrict__ bq,
    const float* __restrict__ Wk, const float* __restrict__ bk,
    const float* __restrict__ Wv, const float* __restrict__ bv,
    int Nrows)
{
    extern __shared__ uint32_t sm[];   // [As0|As1|Bs0|Bs1], stride 36

    const int tid  = threadIdx.x;
    const int lane = tid & 31;
    const int warp = tid >> 5;
    const int wm = warp >> 2;
    const int wn = warp & 3;
    const int bm = blockIdx.x;
    const int bn = blockIdx.y;

    const float* W;  const float* bias;  float* target;
    if (bn < 2)      { W = Wq; bias = bq; target = g_Q; }
    else if (bn < 4) { W = Wk; bias = bk; target = g_K; }
    else             { W = Wv; bias = bv; target = g_V; }
    const int ncol0 = (bn & 1) * 128;

    float acc[4][4][4];
    #pragma unroll
    for (int i = 0; i < 4; i++)
        #pragma unroll
        for (int j = 0; j < 4; j++)
            #pragma unroll
            for (int k = 0; k < 4; k++) acc[i][j][k] = 0.0f;

    const int lr = tid >> 3;          // 0..31
    const int lc = (tid & 7) * 4;     // 0,4,..,28

    const uint32_t smem_base = (uint32_t)__cvta_generic_to_shared(sm);

    auto load_stage = [&](int kb, int s) {
        #pragma unroll
        for (int i = 0; i < 4; i++) {
            int r = lr + i * 32;
            int grow = bm * 128 + r;
            const float* gp = h + (size_t)grow * 256 + kb + lc;
            uint32_t sa = smem_base + (uint32_t)((s * GSTAGE + r * 36 + lc) * 4);
            cp_async16(sa, gp, (grow < Nrows) ? 16 : 0);
        }
        #pragma unroll
        for (int i = 0; i < 4; i++) {
            int r = lr + i * 32;
            const float* gp = W + (size_t)(ncol0 + r) * 256 + kb + lc;
            uint32_t sa = smem_base + (uint32_t)((2 * GSTAGE + s * GSTAGE + r * 36 + lc) * 4);
            cp_async16(sa, gp, 16);
        }
        asm volatile("cp.async.commit_group;" ::: "memory");
    };

    load_stage(0, 0);

    for (int it = 0; it < 8; it++) {
        const int p = it & 1;
        if (it + 1 < 8) {
            load_stage((it + 1) * 32, 1 - p);
            asm volatile("cp.async.wait_group 1;" ::: "memory");
        } else {
            asm volatile("cp.async.wait_group 0;" ::: "memory");
        }
        __syncthreads();

        const uint32_t* A = sm + p * GSTAGE;
        const uint32_t* B = sm + 2 * GSTAGE + p * GSTAGE;

        #pragma unroll
        for (int ks = 0; ks < 4; ks++) {
            const int k0 = ks * 8;
            uint32_t a[4][4], b[4][2];
            #pragma unroll
            for (int mt = 0; mt < 4; mt++) {
                int r = wm * 64 + mt * 16 + (lane >> 2);
                int c = k0 + (lane & 3);
                a[mt][0] = f2tf32(__uint_as_float(A[r * 36 + c]));
                a[mt][1] = f2tf32(__uint_as_float(A[(r + 8) * 36 + c]));
                a[mt][2] = f2tf32(__uint_as_float(A[r * 36 + c + 4]));
                a[mt][3] = f2tf32(__uint_as_float(A[(r + 8) * 36 + c + 4]));
            }
            #pragma unroll
            for (int nt = 0; nt < 4; nt++) {
                int n = wn * 32 + nt * 8 + (lane >> 2);
                int c = k0 + (lane & 3);
                b[nt][0] = f2tf32(__uint_as_float(B[n * 36 + c]));
                b[nt][1] = f2tf32(__uint_as_float(B[n * 36 + c + 4]));
            }
            #pragma unroll
            for (int mt = 0; mt < 4; mt++)
                #pragma unroll
                for (int nt = 0; nt < 4; nt++)
                    asm volatile(
                        "mma.sync.aligned.m16n8k8.row.col.f32.tf32.tf32.f32 "
                        "{%0,%1,%2,%3}, {%4,%5,%6,%7}, {%8,%9}, {%0,%1,%2,%3};"
                        : "+f"(acc[mt][nt][0]), "+f"(acc[mt][nt][1]),
                          "+f"(acc[mt][nt][2]), "+f"(acc[mt][nt][3])
                        : "r"(a[mt][0]), "r"(a[mt][1]), "r"(a[mt][2]), "r"(a[mt][3]),
                          "r"(b[nt][0]), "r"(b[nt][1]));
        }
        __syncthreads();
    }

    #pragma unroll
    for (int mt = 0; mt < 4; mt++) {
        int r0 = wm * 64 + mt * 16 + (lane >> 2);
        #pragma unroll
        for (int nt = 0; nt < 4; nt++) {
            int c0 = wn * 32 + nt * 8 + (lane & 3) * 2;
            #pragma unroll
            for (int cc = 0; cc < 4; cc++) {
                int r = r0 + ((cc >= 2) ? 8 : 0);
                int c = c0 + (cc & 1);
                int grow = bm * 128 + r;
                if (grow < Nrows) {
                    int j = ncol0 + c;
                    target[(size_t)grow * 256 + j] = acc[mt][nt][cc] + bias[j];
                }
            }
        }
    }
}

// ---------------------------------------------------------------------------
// Kernel 2: single-pass fused attention.  One warp per destination node.
// ---------------------------------------------------------------------------
__global__ __launch_bounds__(256) void attn_fused(
    float* __restrict__ out, int n_nodes)
{
    const int node = (blockIdx.x * blockDim.x + threadIdx.x) >> 5;
    if (node >= n_nodes) return;
    const int lane = threadIdx.x & 31;
    const unsigned FULL = 0xffffffffu;
    const float inv = 0.17677669529663687f;   // 1/sqrt(32)

    const int beg = g_rowptr[node];
    const int end = g_rowptr[node + 1];

    const float4* Qr = (const float4*)(g_Q + (size_t)node * 256);
    const float4 q0 = Qr[lane];
    const float4 q1 = Qr[lane + 32];

    float4 acc0 = make_float4(0.f, 0.f, 0.f, 0.f);
    float4 acc1 = make_float4(0.f, 0.f, 0.f, 0.f);
    float z0 = 0.0f, z1 = 0.0f;

    for (int i = beg; i < end; i++) {
        const int s = g_csr_src[i];
        const float4* Kr = (const float4*)(g_K + (size_t)s * 256);
        const float4* Vr = (const float4*)(g_V + (size_t)s * 256);
        float4 k0 = Kr[lane];
        float4 k1 = Kr[lane + 32];
        float4 v0 = Vr[lane];
        float4 v1 = Vr[lane + 32];

        float p0 = k0.x * q0.x + k0.y * q0.y + k0.z * q0.z + k0.w * q0.w;
        float p1 = k1.x * q1.x + k1.y * q1.y + k1.z * q1.z + k1.w * q1.w;
        #pragma unroll
        for (int off = 4; off; off >>= 1) {
            p0 += __shfl_xor_sync(FULL, p0, off);
            p1 += __shfl_xor_sync(FULL, p1, off);
        }
        float sc0 = __expf(fminf(fmaxf(p0 * inv, -5.0f), 5.0f));
        float sc1 = __expf(fminf(fmaxf(p1 * inv, -5.0f), 5.0f));
        z0 += sc0;
        z1 += sc1;

        acc0.x += sc0 * v0.x; acc0.y += sc0 * v0.y;
        acc0.z += sc0 * v0.z; acc0.w += sc0 * v0.w;
        acc1.x += sc1 * v1.x; acc1.y += sc1 * v1.y;
        acc1.z += sc1 * v1.z; acc1.w += sc1 * v1.w;
    }

    const float rz0 = (z0 > 0.0f) ? 1.0f / z0 : 0.0f;
    const float rz1 = (z1 > 0.0f) ? 1.0f / z1 : 0.0f;
    acc0.x *= rz0; acc0.y *= rz0; acc0.z *= rz0; acc0.w *= rz0;
    acc1.x *= rz1; acc1.y *= rz1; acc1.z *= rz1; acc1.w *= rz1;

    float4* o = (float4*)(out + (size_t)node * 256);
    o[lane]      = acc0;
    o[lane + 32] = acc1;
}

// ---------------------------------------------------------------------------
extern "C" void kernel_launch(void* const* d_in, const int* in_sizes, int n_in,
                              void* d_out, int out_size)
{
    const float* h  = (const float*)d_in[0];
    const float* Wq = (const float*)d_in[1];
    const float* bq = (const float*)d_in[2];
    const float* Wk = (const float*)d_in[3];
    const float* bk = (const float*)d_in[4];
    const float* Wv = (const float*)d_in[5];
    const float* bv = (const float*)d_in[6];
    const int*   src = (const int*)d_in[7];
    const int*   dst = (const int*)d_in[8];
    float* out = (float*)d_out;

    const int N = in_sizes[0] / 256;   // 50000
    const int E = in_sizes[7];         // 800000
    const int nb = (N + SCAN_CHUNK - 1) / SCAN_CHUNK;

    // CSR build (parallel 3-phase scan)
    hist_kernel<<<(E + 255) / 256, 256>>>(dst, E);
    scan_part  <<<nb, 1024>>>(N);
    scan_top   <<<1, 64>>>(nb, N);
    scan_final <<<(N + 255) / 256, 256>>>(N);
    scatter_kernel<<<(E + 255) / 256, 256>>>(src, dst, E);

    // QKV projections: pipelined TF32 GEMM (R6 version)
    cudaFuncSetAttribute(qkv_gemm, cudaFuncAttributeMaxDynamicSharedMemorySize,
                         GSMEM_BYTES);
    dim3 grid((N + 127) / 128, 6);
    qkv_gemm<<<grid, 256, GSMEM_BYTES>>>(h, Wq, bq, Wk, bk, Wv, bv, N);

    attn_fused<<<(N * 32 + 255) / 256, 256>>>(out, N);
}

// round 11
// speedup vs baseline: 1.7565x; 1.2085x over previous
#include <cuda_runtime.h>
#include <cuda_fp16.h>
#include <cstdint>
#include <cstddef>

#define NNODES   50000
#define EDGESMAX 800000
#define HDIM     256   // NUM_HEADS * OUT_DIM
#define SCAN_CHUNK 1024
#define NB_SCAN  ((NNODES + SCAN_CHUNK - 1) / SCAN_CHUNK)   // 49

// -------- scratch (static __device__ arrays; no allocation allowed) --------
__device__ float   g_Q[(size_t)NNODES * HDIM];
__device__ __half2 g_Kh[(size_t)NNODES * 128];   // K rows, fp16x2 packed
__device__ __half2 g_Vh[(size_t)NNODES * 128];   // V rows, fp16x2 packed
__device__ int   g_deg[NNODES];        // zero-init at load; scan_final re-zeroes
__device__ int   g_cursor[NNODES];
__device__ int   g_rowptr[NNODES + 1];
__device__ int   g_csr_src[EDGESMAX];
__device__ int   g_bsum[NB_SCAN];
__device__ int   g_boff[NB_SCAN];

__device__ __forceinline__ uint32_t f2tf32(float x) {
    uint32_t r;
    asm("cvt.rna.tf32.f32 %0, %1;" : "=r"(r) : "f"(x));
    return r;
}

__device__ __forceinline__ void cp_async16(uint32_t saddr, const void* gptr, int src_bytes) {
    asm volatile("cp.async.cg.shared.global [%0], [%1], 16, %2;"
                 :: "r"(saddr), "l"(gptr), "r"(src_bytes));
}

// ---------------------------------------------------------------------------
// CSR build: histogram -> 3-phase scan -> scatter
// ---------------------------------------------------------------------------
__global__ void hist_kernel(const int* __restrict__ dst, int E) {
    int e = blockIdx.x * blockDim.x + threadIdx.x;
    if (e < E) atomicAdd(&g_deg[dst[e]], 1);
}

__global__ __launch_bounds__(1024) void scan_part(int n) {
    __shared__ int warp_sums[32];
    const int tid  = threadIdx.x;
    const int lane = tid & 31;
    const int wid  = tid >> 5;
    const int i = blockIdx.x * SCAN_CHUNK + tid;

    int v = (i < n) ? g_deg[i] : 0;
    int x = v;
    #pragma unroll
    for (int off = 1; off < 32; off <<= 1) {
        int t = __shfl_up_sync(0xffffffffu, x, off);
        if (lane >= off) x += t;
    }
    if (lane == 31) warp_sums[wid] = x;
    __syncthreads();
    if (wid == 0) {
        int w = warp_sums[lane];
        #pragma unroll
        for (int off = 1; off < 32; off <<= 1) {
            int t = __shfl_up_sync(0xffffffffu, w, off);
            if (lane >= off) w += t;
        }
        warp_sums[lane] = w;
    }
    __syncthreads();
    int warp_off = (wid > 0) ? warp_sums[wid - 1] : 0;
    if (i < n) g_rowptr[i] = x + warp_off - v;
    if (tid == 1023) g_bsum[blockIdx.x] = x + warp_off;
}

__global__ __launch_bounds__(64) void scan_top(int nb, int n) {
    __shared__ int warp_sums[2];
    const int tid  = threadIdx.x;
    const int lane = tid & 31;
    const int wid  = tid >> 5;
    int v = (tid < nb) ? g_bsum[tid] : 0;
    int x = v;
    #pragma unroll
    for (int off = 1; off < 32; off <<= 1) {
        int t = __shfl_up_sync(0xffffffffu, x, off);
        if (lane >= off) x += t;
    }
    if (lane == 31) warp_sums[wid] = x;
    __syncthreads();
    int carry = (wid == 1) ? warp_sums[0] : 0;
    if (tid < nb) g_boff[tid] = x + carry - v;
    if (tid == nb - 1) g_rowptr[n] = x + carry;
}

__global__ void scan_final(int n) {
    int i = blockIdx.x * blockDim.x + threadIdx.x;
    if (i < n) {
        int r = g_rowptr[i] + g_boff[i >> 10];
        g_rowptr[i] = r;
        g_cursor[i] = r;
        g_deg[i]    = 0;
    }
}

__global__ void scatter_kernel(const int* __restrict__ src,
                               const int* __restrict__ dst, int E) {
    int e = blockIdx.x * blockDim.x + threadIdx.x;
    if (e < E) {
        int pos = atomicAdd(&g_cursor[dst[e]], 1);
        g_csr_src[pos] = src[e];
    }
}

// ---------------------------------------------------------------------------
// Kernel 1: fused QKV projection, 2-stage cp.async pipelined TF32 GEMM.
// Epilogue: Q -> fp32, K/V -> packed fp16x2.
// ---------------------------------------------------------------------------
#define GSTAGE 4608          // 128 * 36 words per tile buffer
#define GSMEM_BYTES (4 * GSTAGE * 4)

__global__ __launch_bounds__(256) void qkv_gemm(
    const float* __restrict__ h,
    const float* __restrict__ Wq, const float* __restrict__ bq,
    const float* __restrict__ Wk, const float* __restrict__ bk,
    const float* __restrict__ Wv, const float* __restrict__ bv,
    int Nrows)
{
    extern __shared__ uint32_t sm[];

    const int tid  = threadIdx.x;
    const int lane = tid & 31;
    const int warp = tid >> 5;
    const int wm = warp >> 2;
    const int wn = warp & 3;
    const int bm = blockIdx.x;
    const int bn = blockIdx.y;

    const float* W;  const float* bias;
    if (bn < 2)      { W = Wq; bias = bq; }
    else if (bn < 4) { W = Wk; bias = bk; }
    else             { W = Wv; bias = bv; }
    const int ncol0 = (bn & 1) * 128;

    float acc[4][4][4];
    #pragma unroll
    for (int i = 0; i < 4; i++)
        #pragma unroll
        for (int j = 0; j < 4; j++)
            #pragma unroll
            for (int k = 0; k < 4; k++) acc[i][j][k] = 0.0f;

    const int lr = tid >> 3;
    const int lc = (tid & 7) * 4;

    const uint32_t smem_base = (uint32_t)__cvta_generic_to_shared(sm);

    auto load_stage = [&](int kb, int s) {
        #pragma unroll
        for (int i = 0; i < 4; i++) {
            int r = lr + i * 32;
            int grow = bm * 128 + r;
            const float* gp = h + (size_t)grow * 256 + kb + lc;
            uint32_t sa = smem_base + (uint32_t)((s * GSTAGE + r * 36 + lc) * 4);
            cp_async16(sa, gp, (grow < Nrows) ? 16 : 0);
        }
        #pragma unroll
        for (int i = 0; i < 4; i++) {
            int r = lr + i * 32;
            const float* gp = W + (size_t)(ncol0 + r) * 256 + kb + lc;
            uint32_t sa = smem_base + (uint32_t)((2 * GSTAGE + s * GSTAGE + r * 36 + lc) * 4);
            cp_async16(sa, gp, 16);
        }
        asm volatile("cp.async.commit_group;" ::: "memory");
    };

    load_stage(0, 0);

    for (int it = 0; it < 8; it++) {
        const int p = it & 1;
        if (it + 1 < 8) {
            load_stage((it + 1) * 32, 1 - p);
            asm volatile("cp.async.wait_group 1;" ::: "memory");
        } else {
            asm volatile("cp.async.wait_group 0;" ::: "memory");
        }
        __syncthreads();

        const uint32_t* A = sm + p * GSTAGE;
        const uint32_t* B = sm + 2 * GSTAGE + p * GSTAGE;

        #pragma unroll
        for (int ks = 0; ks < 4; ks++) {
            const int k0 = ks * 8;
            uint32_t a[4][4], b[4][2];
            #pragma unroll
            for (int mt = 0; mt < 4; mt++) {
                int r = wm * 64 + mt * 16 + (lane >> 2);
                int c = k0 + (lane & 3);
                a[mt][0] = f2tf32(__uint_as_float(A[r * 36 + c]));
                a[mt][1] = f2tf32(__uint_as_float(A[(r + 8) * 36 + c]));
                a[mt][2] = f2tf32(__uint_as_float(A[r * 36 + c + 4]));
                a[mt][3] = f2tf32(__uint_as_float(A[(r + 8) * 36 + c + 4]));
            }
            #pragma unroll
            for (int nt = 0; nt < 4; nt++) {
                int n = wn * 32 + nt * 8 + (lane >> 2);
                int c = k0 + (lane & 3);
                b[nt][0] = f2tf32(__uint_as_float(B[n * 36 + c]));
                b[nt][1] = f2tf32(__uint_as_float(B[n * 36 + c + 4]));
            }
            #pragma unroll
            for (int mt = 0; mt < 4; mt++)
                #pragma unroll
                for (int nt = 0; nt < 4; nt++)
                    asm volatile(
                        "mma.sync.aligned.m16n8k8.row.col.f32.tf32.tf32.f32 "
                        "{%0,%1,%2,%3}, {%4,%5,%6,%7}, {%8,%9}, {%0,%1,%2,%3};"
                        : "+f"(acc[mt][nt][0]), "+f"(acc[mt][nt][1]),
                          "+f"(acc[mt][nt][2]), "+f"(acc[mt][nt][3])
                        : "r"(a[mt][0]), "r"(a[mt][1]), "r"(a[mt][2]), "r"(a[mt][3]),
                          "r"(b[nt][0]), "r"(b[nt][1]));
        }
        __syncthreads();
    }

    // epilogue
    if (bn < 2) {
        // Q: fp32
        #pragma unroll
        for (int mt = 0; mt < 4; mt++) {
            int r0 = wm * 64 + mt * 16 + (lane >> 2);
            #pragma unroll
            for (int nt = 0; nt < 4; nt++) {
                int c0 = wn * 32 + nt * 8 + (lane & 3) * 2;
                #pragma unroll
                for (int cc = 0; cc < 4; cc++) {
                    int r = r0 + ((cc >= 2) ? 8 : 0);
                    int c = c0 + (cc & 1);
                    int grow = bm * 128 + r;
                    if (grow < Nrows) {
                        int j = ncol0 + c;
                        g_Q[(size_t)grow * 256 + j] = acc[mt][nt][cc] + bias[j];
                    }
                }
            }
        }
    } else {
        // K / V: packed fp16x2 (adjacent even/odd columns pack together)
        __half2* targetH = (bn < 4) ? g_Kh : g_Vh;
        #pragma unroll
        for (int mt = 0; mt < 4; mt++) {
            int r0 = wm * 64 + mt * 16 + (lane >> 2);
            #pragma unroll
            for (int nt = 0; nt < 4; nt++) {
                int c0 = wn * 32 + nt * 8 + (lane & 3) * 2;
                int j = ncol0 + c0;
                float b0 = bias[j], b1 = bias[j + 1];
                int grow0 = bm * 128 + r0;
                if (grow0 < Nrows)
                    targetH[(size_t)grow0 * 128 + (j >> 1)] =
                        __float22half2_rn(make_float2(acc[mt][nt][0] + b0,
                                                      acc[mt][nt][1] + b1));
                int grow1 = grow0 + 8;
                if (grow1 < Nrows)
                    targetH[(size_t)grow1 * 128 + (j >> 1)] =
                        __float22half2_rn(make_float2(acc[mt][nt][2] + b0,
                                                      acc[mt][nt][3] + b1));
            }
        }
    }
}

// ---------------------------------------------------------------------------
// Kernel 2: single-pass fused attention with fp16 K/V gather.
// One warp per destination node; each lane owns 8 consecutive channels
// (= one uint4 of fp16x2), one head per lane-quad, 2-shuffle reduction.
// ---------------------------------------------------------------------------
__global__ __launch_bounds__(256) void attn_fused(
    float* __restrict__ out, int n_nodes)
{
    const int node = (blockIdx.x * blockDim.x + threadIdx.x) >> 5;
    if (node >= n_nodes) return;
    const int lane = threadIdx.x & 31;
    const unsigned FULL = 0xffffffffu;
    const float inv = 0.17677669529663687f;   // 1/sqrt(32)

    const int beg = g_rowptr[node];
    const int end = g_rowptr[node + 1];

    // Q channels [8*lane .. 8*lane+7], fp32
    const float4* Qr = (const float4*)(g_Q + (size_t)node * 256);
    const float4 qa = Qr[2 * lane];
    const float4 qb = Qr[2 * lane + 1];

    float4 acca = make_float4(0.f, 0.f, 0.f, 0.f);
    float4 accb = make_float4(0.f, 0.f, 0.f, 0.f);
    float z = 0.0f;                      // this lane's head (uniform per 4-lane group)

    for (int i = beg; i < end; i++) {
        const int s = g_csr_src[i];
        uint4 kr = ((const uint4*)(g_Kh + (size_t)s * 128))[lane];
        uint4 vr = ((const uint4*)(g_Vh + (size_t)s * 128))[lane];

        float2 k0 = __half22float2(*(const __half2*)&kr.x);
        float2 k1 = __half22float2(*(const __half2*)&kr.y);
        float2 k2 = __half22float2(*(const __half2*)&kr.z);
        float2 k3 = __half22float2(*(const __half2*)&kr.w);

        float p = k0.x * qa.x + k0.y * qa.y + k1.x * qa.z + k1.y * qa.w
                + k2.x * qb.x + k2.y * qb.y + k3.x * qb.z + k3.y * qb.w;
        p += __shfl_xor_sync(FULL, p, 1);
        p += __shfl_xor_sync(FULL, p, 2);    // sum over the 4 lanes of this head

        float sc = __expf(fminf(fmaxf(p * inv, -5.0f), 5.0f));
        z += sc;

        float2 v0 = __half22float2(*(const __half2*)&vr.x);
        float2 v1 = __half22float2(*(const __half2*)&vr.y);
        float2 v2 = __half22float2(*(const __half2*)&vr.z);
        float2 v3 = __half22float2(*(const __half2*)&vr.w);

        acca.x += sc * v0.x; acca.y += sc * v0.y;
        acca.z += sc * v1.x; acca.w += sc * v1.y;
        accb.x += sc * v2.x; accb.y += sc * v2.y;
        accb.z += sc * v3.x; accb.w += sc * v3.y;
    }

    const float rz = (z > 0.0f) ? 1.0f / z : 0.0f;
    acca.x *= rz; acca.y *= rz; acca.z *= rz; acca.w *= rz;
    accb.x *= rz; accb.y *= rz; accb.z *= rz; accb.w *= rz;

    float4* o = (float4*)(out + (size_t)node * 256);
    o[2 * lane]     = acca;
    o[2 * lane + 1] = accb;
}

// ---------------------------------------------------------------------------
extern "C" void kernel_launch(void* const* d_in, const int* in_sizes, int n_in,
                              void* d_out, int out_size)
{
    const float* h  = (const float*)d_in[0];
    const float* Wq = (const float*)d_in[1];
    const float* bq = (const float*)d_in[2];
    const float* Wk = (const float*)d_in[3];
    const float* bk = (const float*)d_in[4];
    const float* Wv = (const float*)d_in[5];
    const float* bv = (const float*)d_in[6];
    const int*   src = (const int*)d_in[7];
    const int*   dst = (const int*)d_in[8];
    float* out = (float*)d_out;

    const int N = in_sizes[0] / 256;   // 50000
    const int E = in_sizes[7];         // 800000
    const int nb = (N + SCAN_CHUNK - 1) / SCAN_CHUNK;

    // CSR build (parallel 3-phase scan)
    hist_kernel<<<(E + 255) / 256, 256>>>(dst, E);
    scan_part  <<<nb, 1024>>>(N);
    scan_top   <<<1, 64>>>(nb, N);
    scan_final <<<(N + 255) / 256, 256>>>(N);
    scatter_kernel<<<(E + 255) / 256, 256>>>(src, dst, E);

    // QKV projections: pipelined TF32 GEMM, fp16-packing epilogue for K/V
    cudaFuncSetAttribute(qkv_gemm, cudaFuncAttributeMaxDynamicSharedMemorySize,
                         GSMEM_BYTES);
    dim3 grid((N + 127) / 128, 6);
    qkv_gemm<<<grid, 256, GSMEM_BYTES>>>(h, Wq, bq, Wk, bk, Wv, bv, N);

    attn_fused<<<(N * 32 + 255) / 256, 256>>>(out, N);
}

// round 12
// speedup vs baseline: 2.0819x; 1.1852x over previous
#include <cuda_runtime.h>
#include <cuda_fp16.h>
#include <cstdint>
#include <cstddef>

#define NNODES   50000
#define EDGESMAX 800000
#define HDIM     256   // NUM_HEADS * OUT_DIM
#define SCAN_CHUNK 1024
#define NB_SCAN  ((NNODES + SCAN_CHUNK - 1) / SCAN_CHUNK)   // 49

// -------- scratch (static __device__ arrays; no allocation allowed) --------
__device__ float   g_Q[(size_t)NNODES * HDIM];
__device__ __half2 g_Kh[(size_t)NNODES * 128];   // K rows, fp16x2 packed
__device__ __half2 g_Vh[(size_t)NNODES * 128];   // V rows, fp16x2 packed
__device__ __half  g_hH[(size_t)NNODES * HDIM];  // h converted to fp16
__device__ __half  g_wH[(size_t)3 * HDIM * 256]; // Wq|Wk|Wv converted to fp16
__device__ int   g_deg[NNODES];        // zero-init at load; scan_final re-zeroes
__device__ int   g_cursor[NNODES];
__device__ int   g_rowptr[NNODES + 1];
__device__ int   g_csr_src[EDGESMAX];
__device__ int   g_bsum[NB_SCAN];
__device__ int   g_boff[NB_SCAN];

__device__ __forceinline__ void cp_async16(uint32_t saddr, const void* gptr, int src_bytes) {
    asm volatile("cp.async.cg.shared.global [%0], [%1], 16, %2;"
                 :: "r"(saddr), "l"(gptr), "r"(src_bytes));
}

// ---------------------------------------------------------------------------
// fp32 -> fp16 conversion pre-passes (vectorized)
// ---------------------------------------------------------------------------
__global__ void conv_h(const float4* __restrict__ h4, int n4) {
    int i = blockIdx.x * blockDim.x + threadIdx.x;
    if (i < n4) {
        float4 v = h4[i];
        __half2* o = (__half2*)g_hH;
        o[2 * i]     = __float22half2_rn(make_float2(v.x, v.y));
        o[2 * i + 1] = __float22half2_rn(make_float2(v.z, v.w));
    }
}

__global__ void conv_w(const float4* __restrict__ Wq4,
                       const float4* __restrict__ Wk4,
                       const float4* __restrict__ Wv4) {
    // each W is 256*256 floats = 16384 float4
    int i = blockIdx.x * blockDim.x + threadIdx.x;   // 0 .. 3*16384
    int m = i >> 14, r = i & 16383;
    const float4* W4 = (m == 0) ? Wq4 : (m == 1) ? Wk4 : Wv4;
    float4 v = W4[r];
    __half2* o = (__half2*)(g_wH + (size_t)m * 65536);
    o[2 * r]     = __float22half2_rn(make_float2(v.x, v.y));
    o[2 * r + 1] = __float22half2_rn(make_float2(v.z, v.w));
}

// ---------------------------------------------------------------------------
// CSR build: histogram -> 3-phase scan -> scatter
// ---------------------------------------------------------------------------
__global__ void hist_kernel(const int* __restrict__ dst, int E) {
    int e = blockIdx.x * blockDim.x + threadIdx.x;
    if (e < E) atomicAdd(&g_deg[dst[e]], 1);
}

__global__ __launch_bounds__(1024) void scan_part(int n) {
    __shared__ int warp_sums[32];
    const int tid  = threadIdx.x;
    const int lane = tid & 31;
    const int wid  = tid >> 5;
    const int i = blockIdx.x * SCAN_CHUNK + tid;

    int v = (i < n) ? g_deg[i] : 0;
    int x = v;
    #pragma unroll
    for (int off = 1; off < 32; off <<= 1) {
        int t = __shfl_up_sync(0xffffffffu, x, off);
        if (lane >= off) x += t;
    }
    if (lane == 31) warp_sums[wid] = x;
    __syncthreads();
    if (wid == 0) {
        int w = warp_sums[lane];
        #pragma unroll
        for (int off = 1; off < 32; off <<= 1) {
            int t = __shfl_up_sync(0xffffffffu, w, off);
            if (lane >= off) w += t;
        }
        warp_sums[lane] = w;
    }
    __syncthreads();
    int warp_off = (wid > 0) ? warp_sums[wid - 1] : 0;
    if (i < n) g_rowptr[i] = x + warp_off - v;
    if (tid == 1023) g_bsum[blockIdx.x] = x + warp_off;
}

__global__ __launch_bounds__(64) void scan_top(int nb, int n) {
    __shared__ int warp_sums[2];
    const int tid  = threadIdx.x;
    const int lane = tid & 31;
    const int wid  = tid >> 5;
    int v = (tid < nb) ? g_bsum[tid] : 0;
    int x = v;
    #pragma unroll
    for (int off = 1; off < 32; off <<= 1) {
        int t = __shfl_up_sync(0xffffffffu, x, off);
        if (lane >= off) x += t;
    }
    if (lane == 31) warp_sums[wid] = x;
    __syncthreads();
    int carry = (wid == 1) ? warp_sums[0] : 0;
    if (tid < nb) g_boff[tid] = x + carry - v;
    if (tid == nb - 1) g_rowptr[n] = x + carry;
}

__global__ void scan_final(int n) {
    int i = blockIdx.x * blockDim.x + threadIdx.x;
    if (i < n) {
        int r = g_rowptr[i] + g_boff[i >> 10];
        g_rowptr[i] = r;
        g_cursor[i] = r;
        g_deg[i]    = 0;
    }
}

__global__ void scatter_kernel(const int* __restrict__ src,
                               const int* __restrict__ dst, int E) {
    int e = blockIdx.x * blockDim.x + threadIdx.x;
    if (e < E) {
        int pos = atomicAdd(&g_cursor[dst[e]], 1);
        g_csr_src[pos] = src[e];
    }
}

// ---------------------------------------------------------------------------
// Kernel 1: fused QKV projection, fp16 m16n8k16 MMA, fp32 accumulate.
// 2-stage cp.async double buffering. Block tile 128x128x32, warp tile 64x32.
// smem rows: 32 halves = 64B + 16B pad -> stride 20 u32 (conflict-free).
// ---------------------------------------------------------------------------
#define HSTRIDE 20
#define HSTAGE  (128 * HSTRIDE)                 // u32 per tile buffer
#define GSMEM_BYTES (4 * HSTAGE * 4)            // A0|A1|B0|B1

__global__ __launch_bounds__(256) void qkv_gemm(
    const float* __restrict__ bq, const float* __restrict__ bk,
    const float* __restrict__ bv, int Nrows)
{
    extern __shared__ uint32_t sm[];

    const int tid  = threadIdx.x;
    const int lane = tid & 31;
    const int warp = tid >> 5;
    const int wm = warp >> 2;          // 0..1
    const int wn = warp & 3;           // 0..3
    const int bm = blockIdx.x;
    const int bn = blockIdx.y;

    const float* bias;
    if (bn < 2)      bias = bq;
    else if (bn < 4) bias = bk;
    else             bias = bv;
    const int ncol0 = (bn & 1) * 128;
    const __half* Wp = g_wH + (size_t)(bn >> 1) * 65536;

    float acc[4][4][4];
    #pragma unroll
    for (int i = 0; i < 4; i++)
        #pragma unroll
        for (int j = 0; j < 4; j++)
            #pragma unroll
            for (int k = 0; k < 4; k++) acc[i][j][k] = 0.0f;

    const int lrow = tid >> 2;         // 0..63 (two passes for 128 rows)
    const int lchk = tid & 3;          // 16B chunk within 64B row

    const uint32_t smem_base = (uint32_t)__cvta_generic_to_shared(sm);

    auto load_stage = [&](int kb, int s) {
        #pragma unroll
        for (int i = 0; i < 2; i++) {
            int r = lrow + i * 64;
            int grow = bm * 128 + r;
            const __half* gp = g_hH + (size_t)grow * 256 + kb + lchk * 8;
            uint32_t sa = smem_base + (uint32_t)((s * HSTAGE + r * HSTRIDE + lchk * 4) * 4);
            cp_async16(sa, gp, (grow < Nrows) ? 16 : 0);
        }
        #pragma unroll
        for (int i = 0; i < 2; i++) {
            int r = lrow + i * 64;
            const __half* gp = Wp + (size_t)(ncol0 + r) * 256 + kb + lchk * 8;
            uint32_t sa = smem_base + (uint32_t)(((2 + s) * HSTAGE + r * HSTRIDE + lchk * 4) * 4);
            cp_async16(sa, gp, 16);
        }
        asm volatile("cp.async.commit_group;" ::: "memory");
    };

    load_stage(0, 0);

    for (int it = 0; it < 8; it++) {
        const int p = it & 1;
        if (it + 1 < 8) {
            load_stage((it + 1) * 32, 1 - p);
            asm volatile("cp.async.wait_group 1;" ::: "memory");
        } else {
            asm volatile("cp.async.wait_group 0;" ::: "memory");
        }
        __syncthreads();

        const uint32_t* A = sm + p * HSTAGE;
        const uint32_t* B = sm + (2 + p) * HSTAGE;

        #pragma unroll
        for (int ks = 0; ks < 2; ks++) {       // two k16 steps per 32-k block
            const int cu = ks * 8 + (lane & 3);    // u32 col within row
            uint32_t a[4][4], b[4][2];
            #pragma unroll
            for (int mt = 0; mt < 4; mt++) {
                int r = wm * 64 + mt * 16 + (lane >> 2);
                a[mt][0] = A[r * HSTRIDE + cu];
                a[mt][1] = A[(r + 8) * HSTRIDE + cu];
                a[mt][2] = A[r * HSTRIDE + cu + 4];
                a[mt][3] = A[(r + 8) * HSTRIDE + cu + 4];
            }
            #pragma unroll
            for (int nt = 0; nt < 4; nt++) {
                int n = wn * 32 + nt * 8 + (lane >> 2);
                b[nt][0] = B[n * HSTRIDE + cu];
                b[nt][1] = B[n * HSTRIDE + cu + 4];
            }
            #pragma unroll
            for (int mt = 0; mt < 4; mt++)
                #pragma unroll
                for (int nt = 0; nt < 4; nt++)
                    asm volatile(
                        "mma.sync.aligned.m16n8k16.row.col.f32.f16.f16.f32 "
                        "{%0,%1,%2,%3}, {%4,%5,%6,%7}, {%8,%9}, {%0,%1,%2,%3};"
                        : "+f"(acc[mt][nt][0]), "+f"(acc[mt][nt][1]),
                          "+f"(acc[mt][nt][2]), "+f"(acc[mt][nt][3])
                        : "r"(a[mt][0]), "r"(a[mt][1]), "r"(a[mt][2]), "r"(a[mt][3]),
                          "r"(b[nt][0]), "r"(b[nt][1]));
        }
        __syncthreads();
    }

    // epilogue: add bias; Q -> fp32, K/V -> packed fp16x2
    if (bn < 2) {
        #pragma unroll
        for (int mt = 0; mt < 4; mt++) {
            int r0 = wm * 64 + mt * 16 + (lane >> 2);
            #pragma unroll
            for (int nt = 0; nt < 4; nt++) {
                int c0 = wn * 32 + nt * 8 + (lane & 3) * 2;
                #pragma unroll
                for (int cc = 0; cc < 4; cc++) {
                    int r = r0 + ((cc >= 2) ? 8 : 0);
                    int c = c0 + (cc & 1);
                    int grow = bm * 128 + r;
                    if (grow < Nrows) {
                        int j = ncol0 + c;
                        g_Q[(size_t)grow * 256 + j] = acc[mt][nt][cc] + bias[j];
                    }
                }
            }
        }
    } else {
        __half2* targetH = (bn < 4) ? g_Kh : g_Vh;
        #pragma unroll
        for (int mt = 0; mt < 4; mt++) {
            int r0 = wm * 64 + mt * 16 + (lane >> 2);
            #pragma unroll
            for (int nt = 0; nt < 4; nt++) {
                int c0 = wn * 32 + nt * 8 + (lane & 3) * 2;
                int j = ncol0 + c0;
                float b0 = bias[j], b1 = bias[j + 1];
                int grow0 = bm * 128 + r0;
                if (grow0 < Nrows)
                    targetH[(size_t)grow0 * 128 + (j >> 1)] =
                        __float22half2_rn(make_float2(acc[mt][nt][0] + b0,
                                                      acc[mt][nt][1] + b1));
                int grow1 = grow0 + 8;
                if (grow1 < Nrows)
                    targetH[(size_t)grow1 * 128 + (j >> 1)] =
                        __float22half2_rn(make_float2(acc[mt][nt][2] + b0,
                                                      acc[mt][nt][3] + b1));
            }
        }
    }
}

// ---------------------------------------------------------------------------
// Kernel 2: single-pass fused attention with fp16 K/V gather.
// One warp per destination node; lane owns 8 channels, one head per lane-quad.
// ---------------------------------------------------------------------------
__global__ __launch_bounds__(256) void attn_fused(
    float* __restrict__ out, int n_nodes)
{
    const int node = (blockIdx.x * blockDim.x + threadIdx.x) >> 5;
    if (node >= n_nodes) return;
    const int lane = threadIdx.x & 31;
    const unsigned FULL = 0xffffffffu;
    const float inv = 0.17677669529663687f;   // 1/sqrt(32)

    const int beg = g_rowptr[node];
    const int end = g_rowptr[node + 1];

    const float4* Qr = (const float4*)(g_Q + (size_t)node * 256);
    const float4 qa = Qr[2 * lane];
    const float4 qb = Qr[2 * lane + 1];

    float4 acca = make_float4(0.f, 0.f, 0.f, 0.f);
    float4 accb = make_float4(0.f, 0.f, 0.f, 0.f);
    float z = 0.0f;

    for (int i = beg; i < end; i++) {
        const int s = g_csr_src[i];
        uint4 kr = ((const uint4*)(g_Kh + (size_t)s * 128))[lane];
        uint4 vr = ((const uint4*)(g_Vh + (size_t)s * 128))[lane];

        float2 k0 = __half22float2(*(const __half2*)&kr.x);
        float2 k1 = __half22float2(*(const __half2*)&kr.y);
        float2 k2 = __half22float2(*(const __half2*)&kr.z);
        float2 k3 = __half22float2(*(const __half2*)&kr.w);

        float p = k0.x * qa.x + k0.y * qa.y + k1.x * qa.z + k1.y * qa.w
                + k2.x * qb.x + k2.y * qb.y + k3.x * qb.z + k3.y * qb.w;
        p += __shfl_xor_sync(FULL, p, 1);
        p += __shfl_xor_sync(FULL, p, 2);

        float sc = __expf(fminf(fmaxf(p * inv, -5.0f), 5.0f));
        z += sc;

        float2 v0 = __half22float2(*(const __half2*)&vr.x);
        float2 v1 = __half22float2(*(const __half2*)&vr.y);
        float2 v2 = __half22float2(*(const __half2*)&vr.z);
        float2 v3 = __half22float2(*(const __half2*)&vr.w);

        acca.x += sc * v0.x; acca.y += sc * v0.y;
        acca.z += sc * v1.x; acca.w += sc * v1.y;
        accb.x += sc * v2.x; accb.y += sc * v2.y;
        accb.z += sc * v3.x; accb.w += sc * v3.y;
    }

    const float rz = (z > 0.0f) ? 1.0f / z : 0.0f;
    acca.x *= rz; acca.y *= rz; acca.z *= rz; acca.w *= rz;
    accb.x *= rz; accb.y *= rz; accb.z *= rz; accb.w *= rz;

    float4* o = (float4*)(out + (size_t)node * 256);
    o[2 * lane]     = acca;
    o[2 * lane + 1] = accb;
}

// ---------------------------------------------------------------------------
extern "C" void kernel_launch(void* const* d_in, const int* in_sizes, int n_in,
                              void* d_out, int out_size)
{
    const float* h  = (const float*)d_in[0];
    const float* Wq = (const float*)d_in[1];
    const float* bq = (const float*)d_in[2];
    const float* Wk = (const float*)d_in[3];
    const float* bk = (const float*)d_in[4];
    const float* Wv = (const float*)d_in[5];
    const float* bv = (const float*)d_in[6];
    const int*   src = (const int*)d_in[7];
    const int*   dst = (const int*)d_in[8];
    float* out = (float*)d_out;

    const int N = in_sizes[0] / 256;   // 50000
    const int E = in_sizes[7];         // 800000
    const int nb = (N + SCAN_CHUNK - 1) / SCAN_CHUNK;

    // fp16 conversion pre-passes
    int n4 = N * 64;                   // float4 count of h
    conv_h<<<(n4 + 255) / 256, 256>>>((const float4*)h, n4);
    conv_w<<<(3 * 16384 + 255) / 256, 256>>>((const float4*)Wq,
                                             (const float4*)Wk,
                                             (const float4*)Wv);

    // CSR build (parallel 3-phase scan)
    hist_kernel<<<(E + 255) / 256, 256>>>(dst, E);
    scan_part  <<<nb, 1024>>>(N);
    scan_top   <<<1, 64>>>(nb, N);
    scan_final <<<(N + 255) / 256, 256>>>(N);
    scatter_kernel<<<(E + 255) / 256, 256>>>(src, dst, E);

    // QKV projections: fp16 tensor-core GEMM
    cudaFuncSetAttribute(qkv_gemm, cudaFuncAttributeMaxDynamicSharedMemorySize,
                         GSMEM_BYTES);
    dim3 grid((N + 127) / 128, 6);
    qkv_gemm<<<grid, 256, GSMEM_BYTES>>>(bq, bk, bv, N);

    attn_fused<<<(N * 32 + 255) / 256, 256>>>(out, N);
}

// round 13
// speedup vs baseline: 2.0847x; 1.0014x over previous
#include <cuda_runtime.h>
#include <cuda_fp16.h>
#include <cstdint>
#include <cstddef>

#define NNODES   50000
#define EDGESMAX 800000
#define HDIM     256   // NUM_HEADS * OUT_DIM
#define SCAN_CHUNK 1024
#define NB_SCAN  ((NNODES + SCAN_CHUNK - 1) / SCAN_CHUNK)   // 49

// -------- scratch (static __device__ arrays; no allocation allowed) --------
__device__ float   g_Q[(size_t)NNODES * HDIM];
__device__ __half2 g_Kh[(size_t)NNODES * 128];   // K rows, fp16x2 packed
__device__ __half2 g_Vh[(size_t)NNODES * 128];   // V rows, fp16x2 packed
__device__ __half  g_hH[(size_t)NNODES * HDIM];  // h converted to fp16
__device__ __half  g_wH[(size_t)3 * HDIM * 256]; // Wq|Wk|Wv converted to fp16
__device__ int   g_deg[NNODES];        // zero-init at load; scan_final re-zeroes
__device__ int   g_cursor[NNODES];
__device__ int   g_rowptr[NNODES + 1];
__device__ int   g_csr_src[EDGESMAX];
__device__ int   g_bsum[NB_SCAN];
__device__ int   g_boff[NB_SCAN];

__device__ __forceinline__ void cp_async16(uint32_t saddr, const void* gptr, int src_bytes) {
    asm volatile("cp.async.cg.shared.global [%0], [%1], 16, %2;"
                 :: "r"(saddr), "l"(gptr), "r"(src_bytes));
}

// ---------------------------------------------------------------------------
// fp32 -> fp16 conversion pre-passes (vectorized)
// ---------------------------------------------------------------------------
__global__ void conv_h(const float4* __restrict__ h4, int n4) {
    int i = blockIdx.x * blockDim.x + threadIdx.x;
    if (i < n4) {
        float4 v = h4[i];
        __half2* o = (__half2*)g_hH;
        o[2 * i]     = __float22half2_rn(make_float2(v.x, v.y));
        o[2 * i + 1] = __float22half2_rn(make_float2(v.z, v.w));
    }
}

__global__ void conv_w(const float4* __restrict__ Wq4,
                       const float4* __restrict__ Wk4,
                       const float4* __restrict__ Wv4) {
    int i = blockIdx.x * blockDim.x + threadIdx.x;   // 0 .. 3*16384
    int m = i >> 14, r = i & 16383;
    const float4* W4 = (m == 0) ? Wq4 : (m == 1) ? Wk4 : Wv4;
    float4 v = W4[r];
    __half2* o = (__half2*)(g_wH + (size_t)m * 65536);
    o[2 * r]     = __float22half2_rn(make_float2(v.x, v.y));
    o[2 * r + 1] = __float22half2_rn(make_float2(v.z, v.w));
}

// ---------------------------------------------------------------------------
// CSR build: histogram -> 3-phase scan -> scatter
// ---------------------------------------------------------------------------
__global__ void hist_kernel(const int* __restrict__ dst, int E) {
    int e = blockIdx.x * blockDim.x + threadIdx.x;
    if (e < E) atomicAdd(&g_deg[dst[e]], 1);
}

__global__ __launch_bounds__(1024) void scan_part(int n) {
    __shared__ int warp_sums[32];
    const int tid  = threadIdx.x;
    const int lane = tid & 31;
    const int wid  = tid >> 5;
    const int i = blockIdx.x * SCAN_CHUNK + tid;

    int v = (i < n) ? g_deg[i] : 0;
    int x = v;
    #pragma unroll
    for (int off = 1; off < 32; off <<= 1) {
        int t = __shfl_up_sync(0xffffffffu, x, off);
        if (lane >= off) x += t;
    }
    if (lane == 31) warp_sums[wid] = x;
    __syncthreads();
    if (wid == 0) {
        int w = warp_sums[lane];
        #pragma unroll
        for (int off = 1; off < 32; off <<= 1) {
            int t = __shfl_up_sync(0xffffffffu, w, off);
            if (lane >= off) w += t;
        }
        warp_sums[lane] = w;
    }
    __syncthreads();
    int warp_off = (wid > 0) ? warp_sums[wid - 1] : 0;
    if (i < n) g_rowptr[i] = x + warp_off - v;
    if (tid == 1023) g_bsum[blockIdx.x] = x + warp_off;
}

__global__ __launch_bounds__(64) void scan_top(int nb, int n) {
    __shared__ int warp_sums[2];
    const int tid  = threadIdx.x;
    const int lane = tid & 31;
    const int wid  = tid >> 5;
    int v = (tid < nb) ? g_bsum[tid] : 0;
    int x = v;
    #pragma unroll
    for (int off = 1; off < 32; off <<= 1) {
        int t = __shfl_up_sync(0xffffffffu, x, off);
        if (lane >= off) x += t;
    }
    if (lane == 31) warp_sums[wid] = x;
    __syncthreads();
    int carry = (wid == 1) ? warp_sums[0] : 0;
    if (tid < nb) g_boff[tid] = x + carry - v;
    if (tid == nb - 1) g_rowptr[n] = x + carry;
}

__global__ void scan_final(int n) {
    int i = blockIdx.x * blockDim.x + threadIdx.x;
    if (i < n) {
        int r = g_rowptr[i] + g_boff[i >> 10];
        g_rowptr[i] = r;
        g_cursor[i] = r;
        g_deg[i]    = 0;
    }
}

__global__ void scatter_kernel(const int* __restrict__ src,
                               const int* __restrict__ dst, int E) {
    int e = blockIdx.x * blockDim.x + threadIdx.x;
    if (e < E) {
        int pos = atomicAdd(&g_cursor[dst[e]], 1);
        g_csr_src[pos] = src[e];
    }
}

// ---------------------------------------------------------------------------
// Kernel 1: A-resident fused QKV GEMM, fp16 m16n8k16, ldmatrix fragments.
// grid (391, 2).  Each CTA: loads its 128x256 fp16 A tile once (stride
// 528 B, conflict-free for ldmatrix), then loops Q,K,V streaming B in
// double-buffered 8 KB stages.
// ---------------------------------------------------------------------------
#define A_STRIDE_U32 132                 // 128 data u32 + 4 pad (528 B/row)
#define A_U32        (128 * A_STRIDE_U32)
#define B_STRIDE_U32 20                  // 16 data u32 + 4 pad (80 B/row)
#define B_U32        (128 * B_STRIDE_U32)
#define GSMEM_BYTES  ((A_U32 + 2 * B_U32) * 4)   // 88064 B

__global__ __launch_bounds__(256, 2) void qkv_gemm(
    const float* __restrict__ bq, const float* __restrict__ bk,
    const float* __restrict__ bv, int Nrows)
{
    extern __shared__ uint32_t sm[];     // [A | B0 | B1]
    uint32_t* Bs = sm + A_U32;

    const int tid  = threadIdx.x;
    const int lane = tid & 31;
    const int warp = tid >> 5;
    const int wm = warp >> 2;            // 0..1
    const int wn = warp & 3;             // 0..3
    const int bm = blockIdx.x;
    const int ncol0 = blockIdx.y * 128;

    const uint32_t smem_base  = (uint32_t)__cvta_generic_to_shared(sm);
    const uint32_t smem_Bbase = smem_base + A_U32 * 4;

    // ---- load full A tile (128 rows x 512B) via cp.async ----
    {
        #pragma unroll
        for (int i = 0; i < 16; i++) {
            int c = tid + i * 256;           // 0..4095 chunks of 16B
            int r = c >> 5, chk = c & 31;
            int grow = bm * 128 + r;
            const __half* gp = g_hH + (size_t)grow * 256 + chk * 8;
            uint32_t sa = smem_base + (uint32_t)(r * A_STRIDE_U32 * 4 + chk * 16);
            cp_async16(sa, gp, (grow < Nrows) ? 16 : 0);
        }
    }
    // ---- load B stage for global stage g into buffer ----
    auto load_B = [&](int g, int buf) {
        int w = g >> 3, it = g & 7;
        const __half* Wp = g_wH + (size_t)w * 65536;
        #pragma unroll
        for (int i = 0; i < 2; i++) {
            int c = tid + i * 256;           // 0..511 chunks
            int r = c >> 2, chk = c & 3;
            const __half* gp = Wp + (size_t)(ncol0 + r) * 256 + it * 32 + chk * 8;
            uint32_t sa = smem_Bbase + (uint32_t)(buf * B_U32 * 4 + r * B_STRIDE_U32 * 4 + chk * 16);
            cp_async16(sa, gp, 16);
        }
    };

    load_B(0, 0);
    asm volatile("cp.async.commit_group;" ::: "memory");   // G0 = A + B(0)

    // per-lane ldmatrix base addresses
    uint32_t aAddr[4];
    #pragma unroll
    for (int mt = 0; mt < 4; mt++) {
        int rowA = wm * 64 + mt * 16 + (lane & 7) + ((lane >> 3) & 1) * 8;
        aAddr[mt] = smem_base + (uint32_t)(rowA * A_STRIDE_U32 * 4 + ((lane >> 4) * 8) * 2);
    }
    uint32_t bAddrBase[4];
    #pragma unroll
    for (int nt = 0; nt < 4; nt++) {
        int rowB = wn * 32 + nt * 8 + (lane & 7);
        bAddrBase[nt] = (uint32_t)(rowB * B_STRIDE_U32 * 4 + (((lane >> 3) & 1) * 8) * 2);
    }

    float acc[4][4][4];
    const float* biases[3] = {bq, bk, bv};

    for (int w = 0; w < 3; w++) {
        #pragma unroll
        for (int i = 0; i < 4; i++)
            #pragma unroll
            for (int j = 0; j < 4; j++)
                #pragma unroll
                for (int k = 0; k < 4; k++) acc[i][j][k] = 0.0f;

        for (int it = 0; it < 8; it++) {
            const int g = w * 8 + it;
            if (g + 1 < 24) {
                load_B(g + 1, (g + 1) & 1);
                asm volatile("cp.async.commit_group;" ::: "memory");
                asm volatile("cp.async.wait_group 1;" ::: "memory");
            } else {
                asm volatile("cp.async.wait_group 0;" ::: "memory");
            }
            __syncthreads();

            const uint32_t bStage = smem_Bbase + (uint32_t)((g & 1) * B_U32 * 4);

            #pragma unroll
            for (int ks = 0; ks < 2; ks++) {
                const int kOffA = (it * 32 + ks * 16) * 2;   // bytes
                const int kOffB = (ks * 16) * 2;
                uint32_t a[4][4], b[4][2];
                #pragma unroll
                for (int mt = 0; mt < 4; mt++)
                    asm volatile(
                        "ldmatrix.sync.aligned.m8n8.x4.shared.b16 {%0,%1,%2,%3}, [%4];"
                        : "=r"(a[mt][0]), "=r"(a[mt][1]), "=r"(a[mt][2]), "=r"(a[mt][3])
                        : "r"(aAddr[mt] + kOffA));
                #pragma unroll
                for (int nt = 0; nt < 4; nt++)
                    asm volatile(
                        "ldmatrix.sync.aligned.m8n8.x2.shared.b16 {%0,%1}, [%2];"
                        : "=r"(b[nt][0]), "=r"(b[nt][1])
                        : "r"(bStage + bAddrBase[nt] + kOffB));
                #pragma unroll
                for (int mt = 0; mt < 4; mt++)
                    #pragma unroll
                    for (int nt = 0; nt < 4; nt++)
                        asm volatile(
                            "mma.sync.aligned.m16n8k16.row.col.f32.f16.f16.f32 "
                            "{%0,%1,%2,%3}, {%4,%5,%6,%7}, {%8,%9}, {%0,%1,%2,%3};"
                            : "+f"(acc[mt][nt][0]), "+f"(acc[mt][nt][1]),
                              "+f"(acc[mt][nt][2]), "+f"(acc[mt][nt][3])
                            : "r"(a[mt][0]), "r"(a[mt][1]), "r"(a[mt][2]), "r"(a[mt][3]),
                              "r"(b[nt][0]), "r"(b[nt][1]));
            }
            __syncthreads();
        }

        // ---- epilogue for matrix w ----
        const float* bias = biases[w];
        if (w == 0) {
            #pragma unroll
            for (int mt = 0; mt < 4; mt++) {
                int r0 = wm * 64 + mt * 16 + (lane >> 2);
                #pragma unroll
                for (int nt = 0; nt < 4; nt++) {
                    int c0 = wn * 32 + nt * 8 + (lane & 3) * 2;
                    #pragma unroll
                    for (int cc = 0; cc < 4; cc++) {
                        int r = r0 + ((cc >= 2) ? 8 : 0);
                        int c = c0 + (cc & 1);
                        int grow = bm * 128 + r;
                        if (grow < Nrows) {
                            int j = ncol0 + c;
                            g_Q[(size_t)grow * 256 + j] = acc[mt][nt][cc] + bias[j];
                        }
                    }
                }
            }
        } else {
            __half2* targetH = (w == 1) ? g_Kh : g_Vh;
            #pragma unroll
            for (int mt = 0; mt < 4; mt++) {
                int r0 = wm * 64 + mt * 16 + (lane >> 2);
                #pragma unroll
                for (int nt = 0; nt < 4; nt++) {
                    int c0 = wn * 32 + nt * 8 + (lane & 3) * 2;
                    int j = ncol0 + c0;
                    float b0 = bias[j], b1 = bias[j + 1];
                    int grow0 = bm * 128 + r0;
                    if (grow0 < Nrows)
                        targetH[(size_t)grow0 * 128 + (j >> 1)] =
                            __float22half2_rn(make_float2(acc[mt][nt][0] + b0,
                                                          acc[mt][nt][1] + b1));
                    int grow1 = grow0 + 8;
                    if (grow1 < Nrows)
                        targetH[(size_t)grow1 * 128 + (j >> 1)] =
                            __float22half2_rn(make_float2(acc[mt][nt][2] + b0,
                                                          acc[mt][nt][3] + b1));
                }
            }
        }
    }
}

// ---------------------------------------------------------------------------
// Kernel 2: single-pass fused attention with fp16 K/V gather.
// ---------------------------------------------------------------------------
__global__ __launch_bounds__(256) void attn_fused(
    float* __restrict__ out, int n_nodes)
{
    const int node = (blockIdx.x * blockDim.x + threadIdx.x) >> 5;
    if (node >= n_nodes) return;
    const int lane = threadIdx.x & 31;
    const unsigned FULL = 0xffffffffu;
    const float inv = 0.17677669529663687f;   // 1/sqrt(32)

    const int beg = g_rowptr[node];
    const int end = g_rowptr[node + 1];

    const float4* Qr = (const float4*)(g_Q + (size_t)node * 256);
    const float4 qa = Qr[2 * lane];
    const float4 qb = Qr[2 * lane + 1];

    float4 acca = make_float4(0.f, 0.f, 0.f, 0.f);
    float4 accb = make_float4(0.f, 0.f, 0.f, 0.f);
    float z = 0.0f;

    for (int i = beg; i < end; i++) {
        const int s = g_csr_src[i];
        uint4 kr = ((const uint4*)(g_Kh + (size_t)s * 128))[lane];
        uint4 vr = ((const uint4*)(g_Vh + (size_t)s * 128))[lane];

        float2 k0 = __half22float2(*(const __half2*)&kr.x);
        float2 k1 = __half22float2(*(const __half2*)&kr.y);
        float2 k2 = __half22float2(*(const __half2*)&kr.z);
        float2 k3 = __half22float2(*(const __half2*)&kr.w);

        float p = k0.x * qa.x + k0.y * qa.y + k1.x * qa.z + k1.y * qa.w
                + k2.x * qb.x + k2.y * qb.y + k3.x * qb.z + k3.y * qb.w;
        p += __shfl_xor_sync(FULL, p, 1);
        p += __shfl_xor_sync(FULL, p, 2);

        float sc = __expf(fminf(fmaxf(p * inv, -5.0f), 5.0f));
        z += sc;

        float2 v0 = __half22float2(*(const __half2*)&vr.x);
        float2 v1 = __half22float2(*(const __half2*)&vr.y);
        float2 v2 = __half22float2(*(const __half2*)&vr.z);
        float2 v3 = __half22float2(*(const __half2*)&vr.w);

        acca.x += sc * v0.x; acca.y += sc * v0.y;
        acca.z += sc * v1.x; acca.w += sc * v1.y;
        accb.x += sc * v2.x; accb.y += sc * v2.y;
        accb.z += sc * v3.x; accb.w += sc * v3.y;
    }

    const float rz = (z > 0.0f) ? 1.0f / z : 0.0f;
    acca.x *= rz; acca.y *= rz; acca.z *= rz; acca.w *= rz;
    accb.x *= rz; accb.y *= rz; accb.z *= rz; accb.w *= rz;

    float4* o = (float4*)(out + (size_t)node * 256);
    o[2 * lane]     = acca;
    o[2 * lane + 1] = accb;
}

// ---------------------------------------------------------------------------
extern "C" void kernel_launch(void* const* d_in, const int* in_sizes, int n_in,
                              void* d_out, int out_size)
{
    const float* h  = (const float*)d_in[0];
    const float* Wq = (const float*)d_in[1];
    const float* bq = (const float*)d_in[2];
    const float* Wk = (const float*)d_in[3];
    const float* bk = (const float*)d_in[4];
    const float* Wv = (const float*)d_in[5];
    const float* bv = (const float*)d_in[6];
    const int*   src = (const int*)d_in[7];
    const int*   dst = (const int*)d_in[8];
    float* out = (float*)d_out;

    const int N = in_sizes[0] / 256;   // 50000
    const int E = in_sizes[7];         // 800000
    const int nb = (N + SCAN_CHUNK - 1) / SCAN_CHUNK;

    // fp16 conversion pre-passes
    int n4 = N * 64;
    conv_h<<<(n4 + 255) / 256, 256>>>((const float4*)h, n4);
    conv_w<<<(3 * 16384 + 255) / 256, 256>>>((const float4*)Wq,
                                             (const float4*)Wk,
                                             (const float4*)Wv);

    // CSR build (parallel 3-phase scan)
    hist_kernel<<<(E + 255) / 256, 256>>>(dst, E);
    scan_part  <<<nb, 1024>>>(N);
    scan_top   <<<1, 64>>>(nb, N);
    scan_final <<<(N + 255) / 256, 256>>>(N);
    scatter_kernel<<<(E + 255) / 256, 256>>>(src, dst, E);

    // QKV projections: A-resident fp16 tensor-core GEMM
    cudaFuncSetAttribute(qkv_gemm, cudaFuncAttributeMaxDynamicSharedMemorySize,
                         GSMEM_BYTES);
    dim3 grid((N + 127) / 128, 2);
    qkv_gemm<<<grid, 256, GSMEM_BYTES>>>(bq, bk, bv, N);

    attn_fused<<<(N * 32 + 255) / 256, 256>>>(out, N);
}

// round 14
// speedup vs baseline: 2.1258x; 1.0197x over previous
#include <cuda_runtime.h>
#include <cuda_fp16.h>
#include <cstdint>
#include <cstddef>

#define NNODES   50000
#define EDGESMAX 800000
#define HDIM     256   // NUM_HEADS * OUT_DIM
#define SCAN_CHUNK 1024
#define NB_SCAN  ((NNODES + SCAN_CHUNK - 1) / SCAN_CHUNK)   // 49

// -------- scratch (static __device__ arrays; no allocation allowed) --------
__device__ __half2 g_Qh[(size_t)NNODES * 128];   // Q rows, fp16x2 packed
__device__ __half2 g_Kh[(size_t)NNODES * 128];   // K rows, fp16x2 packed
__device__ __half2 g_Vh[(size_t)NNODES * 128];   // V rows, fp16x2 packed
__device__ __half  g_hH[(size_t)NNODES * HDIM];  // h converted to fp16
__device__ __half  g_wH[(size_t)3 * HDIM * 256]; // Wq|Wk|Wv converted to fp16
__device__ int   g_deg[NNODES];        // zero-init at load; scan_final re-zeroes
__device__ int   g_cursor[NNODES];
__device__ int   g_rowptr[NNODES + 1];
__device__ int   g_csr_src[EDGESMAX];
__device__ int   g_bsum[NB_SCAN];
__device__ int   g_boff[NB_SCAN];

__device__ __forceinline__ void cp_async16(uint32_t saddr, const void* gptr, int src_bytes) {
    asm volatile("cp.async.cg.shared.global [%0], [%1], 16, %2;"
                 :: "r"(saddr), "l"(gptr), "r"(src_bytes));
}

// ---------------------------------------------------------------------------
// fused fp32 -> fp16 conversion pre-pass: h then Wq|Wk|Wv
// ---------------------------------------------------------------------------
__global__ void conv_all(const float4* __restrict__ h4,
                         const float4* __restrict__ Wq4,
                         const float4* __restrict__ Wk4,
                         const float4* __restrict__ Wv4, int n4) {
    int i = blockIdx.x * blockDim.x + threadIdx.x;
    if (i < n4) {
        float4 v = h4[i];
        __half2* o = (__half2*)g_hH;
        o[2 * i]     = __float22half2_rn(make_float2(v.x, v.y));
        o[2 * i + 1] = __float22half2_rn(make_float2(v.z, v.w));
    } else {
        int j = i - n4;                        // 0 .. 3*16384-1
        if (j < 3 * 16384) {
            int m = j >> 14, r = j & 16383;
            const float4* W4 = (m == 0) ? Wq4 : (m == 1) ? Wk4 : Wv4;
            float4 v = W4[r];
            __half2* o = (__half2*)(g_wH + (size_t)m * 65536);
            o[2 * r]     = __float22half2_rn(make_float2(v.x, v.y));
            o[2 * r + 1] = __float22half2_rn(make_float2(v.z, v.w));
        }
    }
}

// ---------------------------------------------------------------------------
// CSR build: histogram -> 3-phase scan -> scatter
// ---------------------------------------------------------------------------
__global__ void hist_kernel(const int* __restrict__ dst, int E) {
    int e = blockIdx.x * blockDim.x + threadIdx.x;
    if (e < E) atomicAdd(&g_deg[dst[e]], 1);
}

__global__ __launch_bounds__(1024) void scan_part(int n) {
    __shared__ int warp_sums[32];
    const int tid  = threadIdx.x;
    const int lane = tid & 31;
    const int wid  = tid >> 5;
    const int i = blockIdx.x * SCAN_CHUNK + tid;

    int v = (i < n) ? g_deg[i] : 0;
    int x = v;
    #pragma unroll
    for (int off = 1; off < 32; off <<= 1) {
        int t = __shfl_up_sync(0xffffffffu, x, off);
        if (lane >= off) x += t;
    }
    if (lane == 31) warp_sums[wid] = x;
    __syncthreads();
    if (wid == 0) {
        int w = warp_sums[lane];
        #pragma unroll
        for (int off = 1; off < 32; off <<= 1) {
            int t = __shfl_up_sync(0xffffffffu, w, off);
            if (lane >= off) w += t;
        }
        warp_sums[lane] = w;
    }
    __syncthreads();
    int warp_off = (wid > 0) ? warp_sums[wid - 1] : 0;
    if (i < n) g_rowptr[i] = x + warp_off - v;
    if (tid == 1023) g_bsum[blockIdx.x] = x + warp_off;
}

__global__ __launch_bounds__(64) void scan_top(int nb, int n) {
    __shared__ int warp_sums[2];
    const int tid  = threadIdx.x;
    const int lane = tid & 31;
    const int wid  = tid >> 5;
    int v = (tid < nb) ? g_bsum[tid] : 0;
    int x = v;
    #pragma unroll
    for (int off = 1; off < 32; off <<= 1) {
        int t = __shfl_up_sync(0xffffffffu, x, off);
        if (lane >= off) x += t;
    }
    if (lane == 31) warp_sums[wid] = x;
    __syncthreads();
    int carry = (wid == 1) ? warp_sums[0] : 0;
    if (tid < nb) g_boff[tid] = x + carry - v;
    if (tid == nb - 1) g_rowptr[n] = x + carry;
}

__global__ void scan_final(int n) {
    int i = blockIdx.x * blockDim.x + threadIdx.x;
    if (i < n) {
        int r = g_rowptr[i] + g_boff[i >> 10];
        g_rowptr[i] = r;
        g_cursor[i] = r;
        g_deg[i]    = 0;
    }
}

__global__ void scatter_kernel(const int* __restrict__ src,
                               const int* __restrict__ dst, int E) {
    int e = blockIdx.x * blockDim.x + threadIdx.x;
    if (e < E) {
        int pos = atomicAdd(&g_cursor[dst[e]], 1);
        g_csr_src[pos] = src[e];
    }
}

// ---------------------------------------------------------------------------
// Kernel 1: A-resident fused QKV GEMM, fp16 m16n8k16, ldmatrix fragments.
// grid (391, 2).  Unified half2 epilogue for Q, K and V.
// ---------------------------------------------------------------------------
#define A_STRIDE_U32 132                 // 128 data u32 + 4 pad (528 B/row)
#define A_U32        (128 * A_STRIDE_U32)
#define B_STRIDE_U32 20                  // 16 data u32 + 4 pad (80 B/row)
#define B_U32        (128 * B_STRIDE_U32)
#define GSMEM_BYTES  ((A_U32 + 2 * B_U32) * 4)   // 88064 B

__global__ __launch_bounds__(256, 2) void qkv_gemm(
    const float* __restrict__ bq, const float* __restrict__ bk,
    const float* __restrict__ bv, int Nrows)
{
    extern __shared__ uint32_t sm[];     // [A | B0 | B1]

    const int tid  = threadIdx.x;
    const int lane = tid & 31;
    const int warp = tid >> 5;
    const int wm = warp >> 2;            // 0..1
    const int wn = warp & 3;             // 0..3
    const int bm = blockIdx.x;
    const int ncol0 = blockIdx.y * 128;

    const uint32_t smem_base  = (uint32_t)__cvta_generic_to_shared(sm);
    const uint32_t smem_Bbase = smem_base + A_U32 * 4;

    // ---- load full A tile (128 rows x 512B) via cp.async ----
    {
        #pragma unroll
        for (int i = 0; i < 16; i++) {
            int c = tid + i * 256;           // 0..4095 chunks of 16B
            int r = c >> 5, chk = c & 31;
            int grow = bm * 128 + r;
            const __half* gp = g_hH + (size_t)grow * 256 + chk * 8;
            uint32_t sa = smem_base + (uint32_t)(r * A_STRIDE_U32 * 4 + chk * 16);
            cp_async16(sa, gp, (grow < Nrows) ? 16 : 0);
        }
    }
    auto load_B = [&](int g, int buf) {
        int w = g >> 3, it = g & 7;
        const __half* Wp = g_wH + (size_t)w * 65536;
        #pragma unroll
        for (int i = 0; i < 2; i++) {
            int c = tid + i * 256;           // 0..511 chunks
            int r = c >> 2, chk = c & 3;
            const __half* gp = Wp + (size_t)(ncol0 + r) * 256 + it * 32 + chk * 8;
            uint32_t sa = smem_Bbase + (uint32_t)(buf * B_U32 * 4 + r * B_STRIDE_U32 * 4 + chk * 16);
            cp_async16(sa, gp, 16);
        }
    };

    load_B(0, 0);
    asm volatile("cp.async.commit_group;" ::: "memory");

    // per-lane ldmatrix base addresses
    uint32_t aAddr[4];
    #pragma unroll
    for (int mt = 0; mt < 4; mt++) {
        int rowA = wm * 64 + mt * 16 + (lane & 7) + ((lane >> 3) & 1) * 8;
        aAddr[mt] = smem_base + (uint32_t)(rowA * A_STRIDE_U32 * 4 + ((lane >> 4) * 8) * 2);
    }
    uint32_t bAddrBase[4];
    #pragma unroll
    for (int nt = 0; nt < 4; nt++) {
        int rowB = wn * 32 + nt * 8 + (lane & 7);
        bAddrBase[nt] = (uint32_t)(rowB * B_STRIDE_U32 * 4 + (((lane >> 3) & 1) * 8) * 2);
    }

    float acc[4][4][4];
    const float* biases[3] = {bq, bk, bv};
    __half2* targets[3] = {g_Qh, g_Kh, g_Vh};

    for (int w = 0; w < 3; w++) {
        #pragma unroll
        for (int i = 0; i < 4; i++)
            #pragma unroll
            for (int j = 0; j < 4; j++)
                #pragma unroll
                for (int k = 0; k < 4; k++) acc[i][j][k] = 0.0f;

        for (int it = 0; it < 8; it++) {
            const int g = w * 8 + it;
            if (g + 1 < 24) {
                load_B(g + 1, (g + 1) & 1);
                asm volatile("cp.async.commit_group;" ::: "memory");
                asm volatile("cp.async.wait_group 1;" ::: "memory");
            } else {
                asm volatile("cp.async.wait_group 0;" ::: "memory");
            }
            __syncthreads();

            const uint32_t bStage = smem_Bbase + (uint32_t)((g & 1) * B_U32 * 4);

            #pragma unroll
            for (int ks = 0; ks < 2; ks++) {
                const int kOffA = (it * 32 + ks * 16) * 2;   // bytes
                const int kOffB = (ks * 16) * 2;
                uint32_t a[4][4], b[4][2];
                #pragma unroll
                for (int mt = 0; mt < 4; mt++)
                    asm volatile(
                        "ldmatrix.sync.aligned.m8n8.x4.shared.b16 {%0,%1,%2,%3}, [%4];"
                        : "=r"(a[mt][0]), "=r"(a[mt][1]), "=r"(a[mt][2]), "=r"(a[mt][3])
                        : "r"(aAddr[mt] + kOffA));
                #pragma unroll
                for (int nt = 0; nt < 4; nt++)
                    asm volatile(
                        "ldmatrix.sync.aligned.m8n8.x2.shared.b16 {%0,%1}, [%2];"
                        : "=r"(b[nt][0]), "=r"(b[nt][1])
                        : "r"(bStage + bAddrBase[nt] + kOffB));
                #pragma unroll
                for (int mt = 0; mt < 4; mt++)
                    #pragma unroll
                    for (int nt = 0; nt < 4; nt++)
                        asm volatile(
                            "mma.sync.aligned.m16n8k16.row.col.f32.f16.f16.f32 "
                            "{%0,%1,%2,%3}, {%4,%5,%6,%7}, {%8,%9}, {%0,%1,%2,%3};"
                            : "+f"(acc[mt][nt][0]), "+f"(acc[mt][nt][1]),
                              "+f"(acc[mt][nt][2]), "+f"(acc[mt][nt][3])
                            : "r"(a[mt][0]), "r"(a[mt][1]), "r"(a[mt][2]), "r"(a[mt][3]),
                              "r"(b[nt][0]), "r"(b[nt][1]));
            }
            __syncthreads();
        }

        // ---- unified half2 epilogue ----
        const float* bias = biases[w];
        __half2* targetH = targets[w];
        #pragma unroll
        for (int mt = 0; mt < 4; mt++) {
            int r0 = wm * 64 + mt * 16 + (lane >> 2);
            #pragma unroll
            for (int nt = 0; nt < 4; nt++) {
                int c0 = wn * 32 + nt * 8 + (lane & 3) * 2;
                int j = ncol0 + c0;
                float b0 = bias[j], b1 = bias[j + 1];
                int grow0 = bm * 128 + r0;
                if (grow0 < Nrows)
                    targetH[(size_t)grow0 * 128 + (j >> 1)] =
                        __float22half2_rn(make_float2(acc[mt][nt][0] + b0,
                                                      acc[mt][nt][1] + b1));
                int grow1 = grow0 + 8;
                if (grow1 < Nrows)
                    targetH[(size_t)grow1 * 128 + (j >> 1)] =
                        __float22half2_rn(make_float2(acc[mt][nt][2] + b0,
                                                      acc[mt][nt][3] + b1));
            }
        }
    }
}

// ---------------------------------------------------------------------------
// Kernel 2: single-pass fused attention, all-fp16 gather.
// One warp per destination node; lane owns 8 channels, one head per lane-quad.
// ---------------------------------------------------------------------------
__global__ __launch_bounds__(256) void attn_fused(
    float* __restrict__ out, int n_nodes)
{
    const int node = (blockIdx.x * blockDim.x + threadIdx.x) >> 5;
    if (node >= n_nodes) return;
    const int lane = threadIdx.x & 31;
    const unsigned FULL = 0xffffffffu;
    const float inv = 0.17677669529663687f;   // 1/sqrt(32)

    const int beg = g_rowptr[node];
    const int end = g_rowptr[node + 1];

    // Q channels [8*lane .. 8*lane+7], fp16 -> fp32
    uint4 qr = ((const uint4*)(g_Qh + (size_t)node * 128))[lane];
    float2 q0 = __half22float2(*(const __half2*)&qr.x);
    float2 q1 = __half22float2(*(const __half2*)&qr.y);
    float2 q2 = __half22float2(*(const __half2*)&qr.z);
    float2 q3 = __half22float2(*(const __half2*)&qr.w);

    float4 acca = make_float4(0.f, 0.f, 0.f, 0.f);
    float4 accb = make_float4(0.f, 0.f, 0.f, 0.f);
    float z = 0.0f;

    for (int i = beg; i < end; i++) {
        const int s = g_csr_src[i];
        uint4 kr = ((const uint4*)(g_Kh + (size_t)s * 128))[lane];
        uint4 vr = ((const uint4*)(g_Vh + (size_t)s * 128))[lane];

        float2 k0 = __half22float2(*(const __half2*)&kr.x);
        float2 k1 = __half22float2(*(const __half2*)&kr.y);
        float2 k2 = __half22float2(*(const __half2*)&kr.z);
        float2 k3 = __half22float2(*(const __half2*)&kr.w);

        float p = k0.x * q0.x + k0.y * q0.y + k1.x * q1.x + k1.y * q1.y
                + k2.x * q2.x + k2.y * q2.y + k3.x * q3.x + k3.y * q3.y;
        p += __shfl_xor_sync(FULL, p, 1);
        p += __shfl_xor_sync(FULL, p, 2);

        float sc = __expf(fminf(fmaxf(p * inv, -5.0f), 5.0f));
        z += sc;

        float2 v0 = __half22float2(*(const __half2*)&vr.x);
        float2 v1 = __half22float2(*(const __half2*)&vr.y);
        float2 v2 = __half22float2(*(const __half2*)&vr.z);
        float2 v3 = __half22float2(*(const __half2*)&vr.w);

        acca.x += sc * v0.x; acca.y += sc * v0.y;
        acca.z += sc * v1.x; acca.w += sc * v1.y;
        accb.x += sc * v2.x; accb.y += sc * v2.y;
        accb.z += sc * v3.x; accb.w += sc * v3.y;
    }

    const float rz = (z > 0.0f) ? 1.0f / z : 0.0f;
    acca.x *= rz; acca.y *= rz; acca.z *= rz; acca.w *= rz;
    accb.x *= rz; accb.y *= rz; accb.z *= rz; accb.w *= rz;

    float4* o = (float4*)(out + (size_t)node * 256);
    o[2 * lane]     = acca;
    o[2 * lane + 1] = accb;
}

// ---------------------------------------------------------------------------
extern "C" void kernel_launch(void* const* d_in, const int* in_sizes, int n_in,
                              void* d_out, int out_size)
{
    const float* h  = (const float*)d_in[0];
    const float* Wq = (const float*)d_in[1];
    const float* bq = (const float*)d_in[2];
    const float* Wk = (const float*)d_in[3];
    const float* bk = (const float*)d_in[4];
    const float* Wv = (const float*)d_in[5];
    const float* bv = (const float*)d_in[6];
    const int*   src = (const int*)d_in[7];
    const int*   dst = (const int*)d_in[8];
    float* out = (float*)d_out;

    const int N = in_sizes[0] / 256;   // 50000
    const int E = in_sizes[7];         // 800000
    const int nb = (N + SCAN_CHUNK - 1) / SCAN_CHUNK;

    // fused fp16 conversion pre-pass
    int n4 = N * 64;
    int tot = n4 + 3 * 16384;
    conv_all<<<(tot + 255) / 256, 256>>>((const float4*)h, (const float4*)Wq,
                                         (const float4*)Wk, (const float4*)Wv, n4);

    // CSR build (parallel 3-phase scan)
    hist_kernel<<<(E + 255) / 256, 256>>>(dst, E);
    scan_part  <<<nb, 1024>>>(N);
    scan_top   <<<1, 64>>>(nb, N);
    scan_final <<<(N + 255) / 256, 256>>>(N);
    scatter_kernel<<<(E + 255) / 256, 256>>>(src, dst, E);

    // QKV projections: A-resident fp16 tensor-core GEMM
    cudaFuncSetAttribute(qkv_gemm, cudaFuncAttributeMaxDynamicSharedMemorySize,
                         GSMEM_BYTES);
    dim3 grid((N + 127) / 128, 2);
    qkv_gemm<<<grid, 256, GSMEM_BYTES>>>(bq, bk, bv, N);

    attn_fused<<<(N * 32 + 255) / 256, 256>>>(out, N);
}

// round 15
// speedup vs baseline: 2.2836x; 1.0742x over previous
#include <cuda_runtime.h>
#include <cuda_fp16.h>
#include <cstdint>
#include <cstddef>

#define NNODES   50000
#define EDGESMAX 800000
#define HDIM     256   // NUM_HEADS * OUT_DIM
#define SCAN_CHUNK 1024
#define NB_SCAN  ((NNODES + SCAN_CHUNK - 1) / SCAN_CHUNK)   // 49

// -------- scratch (static __device__ arrays; no allocation allowed) --------
__device__ __half2 g_Qh[(size_t)NNODES * 128];   // Q rows, fp16x2 packed
__device__ __half2 g_Kh[(size_t)NNODES * 128];   // K rows, fp16x2 packed
__device__ __half2 g_Vh[(size_t)NNODES * 128];   // V rows, fp16x2 packed
__device__ __half  g_wH[(size_t)3 * HDIM * 256]; // Wq|Wk|Wv converted to fp16
__device__ int   g_deg[NNODES];        // zero-init at load; scan_final re-zeroes
__device__ int   g_cursor[NNODES];
__device__ int   g_rowptr[NNODES + 1];
__device__ int   g_csr_src[EDGESMAX];
__device__ int   g_bsum[NB_SCAN];
__device__ int   g_boff[NB_SCAN];

__device__ __forceinline__ void cp_async16(uint32_t saddr, const void* gptr) {
    asm volatile("cp.async.cg.shared.global [%0], [%1], 16;"
                 :: "r"(saddr), "l"(gptr));
}

// ---------------------------------------------------------------------------
// fp32 -> fp16 weight conversion (0.8 MB, tiny)
// ---------------------------------------------------------------------------
__global__ void conv_w(const float4* __restrict__ Wq4,
                       const float4* __restrict__ Wk4,
                       const float4* __restrict__ Wv4) {
    int i = blockIdx.x * blockDim.x + threadIdx.x;   // 0 .. 3*16384-1
    if (i < 3 * 16384) {
        int m = i >> 14, r = i & 16383;
        const float4* W4 = (m == 0) ? Wq4 : (m == 1) ? Wk4 : Wv4;
        float4 v = W4[r];
        __half2* o = (__half2*)(g_wH + (size_t)m * 65536);
        o[2 * r]     = __float22half2_rn(make_float2(v.x, v.y));
        o[2 * r + 1] = __float22half2_rn(make_float2(v.z, v.w));
    }
}

// ---------------------------------------------------------------------------
// CSR build: histogram -> 3-phase scan -> scatter
// ---------------------------------------------------------------------------
__global__ void hist_kernel(const int* __restrict__ dst, int E) {
    int e = blockIdx.x * blockDim.x + threadIdx.x;
    if (e < E) atomicAdd(&g_deg[dst[e]], 1);
}

__global__ __launch_bounds__(1024) void scan_part(int n) {
    __shared__ int warp_sums[32];
    const int tid  = threadIdx.x;
    const int lane = tid & 31;
    const int wid  = tid >> 5;
    const int i = blockIdx.x * SCAN_CHUNK + tid;

    int v = (i < n) ? g_deg[i] : 0;
    int x = v;
    #pragma unroll
    for (int off = 1; off < 32; off <<= 1) {
        int t = __shfl_up_sync(0xffffffffu, x, off);
        if (lane >= off) x += t;
    }
    if (lane == 31) warp_sums[wid] = x;
    __syncthreads();
    if (wid == 0) {
        int w = warp_sums[lane];
        #pragma unroll
        for (int off = 1; off < 32; off <<= 1) {
            int t = __shfl_up_sync(0xffffffffu, w, off);
            if (lane >= off) w += t;
        }
        warp_sums[lane] = w;
    }
    __syncthreads();
    int warp_off = (wid > 0) ? warp_sums[wid - 1] : 0;
    if (i < n) g_rowptr[i] = x + warp_off - v;
    if (tid == 1023) g_bsum[blockIdx.x] = x + warp_off;
}

__global__ __launch_bounds__(64) void scan_top(int nb, int n) {
    __shared__ int warp_sums[2];
    const int tid  = threadIdx.x;
    const int lane = tid & 31;
    const int wid  = tid >> 5;
    int v = (tid < nb) ? g_bsum[tid] : 0;
    int x = v;
    #pragma unroll
    for (int off = 1; off < 32; off <<= 1) {
        int t = __shfl_up_sync(0xffffffffu, x, off);
        if (lane >= off) x += t;
    }
    if (lane == 31) warp_sums[wid] = x;
    __syncthreads();
    int carry = (wid == 1) ? warp_sums[0] : 0;
    if (tid < nb) g_boff[tid] = x + carry - v;
    if (tid == nb - 1) g_rowptr[n] = x + carry;
}

__global__ void scan_final(int n) {
    int i = blockIdx.x * blockDim.x + threadIdx.x;
    if (i < n) {
        int r = g_rowptr[i] + g_boff[i >> 10];
        g_rowptr[i] = r;
        g_cursor[i] = r;
        g_deg[i]    = 0;
    }
}

__global__ void scatter_kernel(const int* __restrict__ src,
                               const int* __restrict__ dst, int E) {
    int e = blockIdx.x * blockDim.x + threadIdx.x;
    if (e < E) {
        int pos = atomicAdd(&g_cursor[dst[e]], 1);
        g_csr_src[pos] = src[e];
    }
}

// ---------------------------------------------------------------------------
// Kernel 1: A-resident fused QKV GEMM, fp16 m16n8k16, ldmatrix fragments.
// grid (391, 2).  A tile loaded ONCE per CTA directly from fp32 h (in-kernel
// cvt).  B streamed through a 4-buffer ring, ONE __syncthreads per stage.
// ---------------------------------------------------------------------------
#define A_STRIDE_U32 132                 // 128 data u32 + 4 pad (528 B/row)
#define A_U32        (128 * A_STRIDE_U32)
#define B_STRIDE_U32 20                  // 16 data u32 + 4 pad (80 B/row)
#define B_U32        (128 * B_STRIDE_U32)
#define GSMEM_BYTES  ((A_U32 + 4 * B_U32) * 4)   // 108544 B

__global__ __launch_bounds__(256, 2) void qkv_gemm(
    const float* __restrict__ h,
    const float* __restrict__ bq, const float* __restrict__ bk,
    const float* __restrict__ bv, int Nrows)
{
    extern __shared__ uint32_t sm[];     // [A | B0 | B1 | B2 | B3]

    const int tid  = threadIdx.x;
    const int lane = tid & 31;
    const int warp = tid >> 5;
    const int wm = warp >> 2;            // 0..1
    const int wn = warp & 3;             // 0..3
    const int bm = blockIdx.x;
    const int ncol0 = blockIdx.y * 128;

    const uint32_t smem_base  = (uint32_t)__cvta_generic_to_shared(sm);
    const uint32_t smem_Bbase = smem_base + A_U32 * 4;

    auto load_B = [&](int g, int buf) {
        int w = g >> 3, it = g & 7;
        const __half* Wp = g_wH + (size_t)w * 65536;
        #pragma unroll
        for (int i = 0; i < 2; i++) {
            int c = tid + i * 256;           // 0..511 chunks of 16B
            int r = c >> 2, chk = c & 3;
            const __half* gp = Wp + (size_t)(ncol0 + r) * 256 + it * 32 + chk * 8;
            uint32_t sa = smem_Bbase + (uint32_t)(buf * B_U32 * 4 + r * B_STRIDE_U32 * 4 + chk * 16);
            cp_async16(sa, gp);
        }
        asm volatile("cp.async.commit_group;" ::: "memory");
    };

    // start B stream early (3 stages in flight)
    load_B(0, 0);
    load_B(1, 1);
    load_B(2, 2);

    // ---- load + convert full A tile from fp32 h (once per CTA) ----
    {
        uint32_t* As = sm;
        #pragma unroll
        for (int i = 0; i < 32; i++) {
            int c = tid + i * 256;           // 0..8191 float4 chunks
            int r = c >> 6, f4 = c & 63;
            int grow = bm * 128 + r;
            float4 v = (grow < Nrows)
                     ? ((const float4*)h)[(size_t)grow * 64 + f4]
                     : make_float4(0.f, 0.f, 0.f, 0.f);
            __half2 h0 = __float22half2_rn(make_float2(v.x, v.y));
            __half2 h1 = __float22half2_rn(make_float2(v.z, v.w));
            uint32_t* s = As + r * A_STRIDE_U32 + f4 * 2;
            s[0] = *(uint32_t*)&h0;
            s[1] = *(uint32_t*)&h1;
        }
    }

    // per-lane ldmatrix base addresses
    uint32_t aAddr[4];
    #pragma unroll
    for (int mt = 0; mt < 4; mt++) {
        int rowA = wm * 64 + mt * 16 + (lane & 7) + ((lane >> 3) & 1) * 8;
        aAddr[mt] = smem_base + (uint32_t)(rowA * A_STRIDE_U32 * 4 + ((lane >> 4) * 8) * 2);
    }
    uint32_t bAddrBase[4];
    #pragma unroll
    for (int nt = 0; nt < 4; nt++) {
        int rowB = wn * 32 + nt * 8 + (lane & 7);
        bAddrBase[nt] = (uint32_t)(rowB * B_STRIDE_U32 * 4 + (((lane >> 3) & 1) * 8) * 2);
    }

    float acc[4][4][4];

    for (int g = 0; g < 24; g++) {
        // stage-g completion wait (groups committed so far: 3 + issued loads)
        if (g <= 21)      asm volatile("cp.async.wait_group 2;" ::: "memory");
        else if (g == 22) asm volatile("cp.async.wait_group 1;" ::: "memory");
        else              asm volatile("cp.async.wait_group 0;" ::: "memory");
        __syncthreads();   // B[g] visible; compute of g-1 done -> buf (g-1)&3 free

        if ((g & 7) == 0) {
            #pragma unroll
            for (int i = 0; i < 4; i++)
                #pragma unroll
                for (int j = 0; j < 4; j++)
                    #pragma unroll
                    for (int k = 0; k < 4; k++) acc[i][j][k] = 0.0f;
        }

        if (g + 3 < 24) load_B(g + 3, (g + 3) & 3);

        const int it = g & 7;
        const uint32_t bStage = smem_Bbase + (uint32_t)((g & 3) * B_U32 * 4);

        #pragma unroll
        for (int ks = 0; ks < 2; ks++) {
            const int kOffA = (it * 32 + ks * 16) * 2;   // bytes
            const int kOffB = (ks * 16) * 2;
            uint32_t a[4][4], b[4][2];
            #pragma unroll
            for (int mt = 0; mt < 4; mt++)
                asm volatile(
                    "ldmatrix.sync.aligned.m8n8.x4.shared.b16 {%0,%1,%2,%3}, [%4];"
                    : "=r"(a[mt][0]), "=r"(a[mt][1]), "=r"(a[mt][2]), "=r"(a[mt][3])
                    : "r"(aAddr[mt] + kOffA));
            #pragma unroll
            for (int nt = 0; nt < 4; nt++)
                asm volatile(
                    "ldmatrix.sync.aligned.m8n8.x2.shared.b16 {%0,%1}, [%2];"
                    : "=r"(b[nt][0]), "=r"(b[nt][1])
                    : "r"(bStage + bAddrBase[nt] + kOffB));
            #pragma unroll
            for (int mt = 0; mt < 4; mt++)
                #pragma unroll
                for (int nt = 0; nt < 4; nt++)
                    asm volatile(
                        "mma.sync.aligned.m16n8k16.row.col.f32.f16.f16.f32 "
                        "{%0,%1,%2,%3}, {%4,%5,%6,%7}, {%8,%9}, {%0,%1,%2,%3};"
                        : "+f"(acc[mt][nt][0]), "+f"(acc[mt][nt][1]),
                          "+f"(acc[mt][nt][2]), "+f"(acc[mt][nt][3])
                        : "r"(a[mt][0]), "r"(a[mt][1]), "r"(a[mt][2]), "r"(a[mt][3]),
                          "r"(b[nt][0]), "r"(b[nt][1]));
        }

        if (it == 7) {
            // ---- epilogue for matrix w = g >> 3 ----
            const int w = g >> 3;
            const float* bias = (w == 0) ? bq : (w == 1) ? bk : bv;
            __half2* targetH  = (w == 0) ? g_Qh : (w == 1) ? g_Kh : g_Vh;
            #pragma unroll
            for (int mt = 0; mt < 4; mt++) {
                int r0 = wm * 64 + mt * 16 + (lane >> 2);
                #pragma unroll
                for (int nt = 0; nt < 4; nt++) {
                    int c0 = wn * 32 + nt * 8 + (lane & 3) * 2;
                    int j = ncol0 + c0;
                    float b0 = bias[j], b1 = bias[j + 1];
                    int grow0 = bm * 128 + r0;
                    if (grow0 < Nrows)
                        targetH[(size_t)grow0 * 128 + (j >> 1)] =
                            __float22half2_rn(make_float2(acc[mt][nt][0] + b0,
                                                          acc[mt][nt][1] + b1));
                    int grow1 = grow0 + 8;
                    if (grow1 < Nrows)
                        targetH[(size_t)grow1 * 128 + (j >> 1)] =
                            __float22half2_rn(make_float2(acc[mt][nt][2] + b0,
                                                          acc[mt][nt][3] + b1));
                }
            }
        }
    }
}

// ---------------------------------------------------------------------------
// Kernel 2: single-pass fused attention, all-fp16 gather.
// One warp per destination node; lane owns 8 channels, one head per lane-quad.
// ---------------------------------------------------------------------------
__global__ __launch_bounds__(256) void attn_fused(
    float* __restrict__ out, int n_nodes)
{
    const int node = (blockIdx.x * blockDim.x + threadIdx.x) >> 5;
    if (node >= n_nodes) return;
    const int lane = threadIdx.x & 31;
    const unsigned FULL = 0xffffffffu;
    const float inv = 0.17677669529663687f;   // 1/sqrt(32)

    const int beg = g_rowptr[node];
    const int end = g_rowptr[node + 1];

    uint4 qr = ((const uint4*)(g_Qh + (size_t)node * 128))[lane];
    float2 q0 = __half22float2(*(const __half2*)&qr.x);
    float2 q1 = __half22float2(*(const __half2*)&qr.y);
    float2 q2 = __half22float2(*(const __half2*)&qr.z);
    float2 q3 = __half22float2(*(const __half2*)&qr.w);

    float4 acca = make_float4(0.f, 0.f, 0.f, 0.f);
    float4 accb = make_float4(0.f, 0.f, 0.f, 0.f);
    float z = 0.0f;

    for (int i = beg; i < end; i++) {
        const int s = g_csr_src[i];
        uint4 kr = ((const uint4*)(g_Kh + (size_t)s * 128))[lane];
        uint4 vr = ((const uint4*)(g_Vh + (size_t)s * 128))[lane];

        float2 k0 = __half22float2(*(const __half2*)&kr.x);
        float2 k1 = __half22float2(*(const __half2*)&kr.y);
        float2 k2 = __half22float2(*(const __half2*)&kr.z);
        float2 k3 = __half22float2(*(const __half2*)&kr.w);

        float p = k0.x * q0.x + k0.y * q0.y + k1.x * q1.x + k1.y * q1.y
                + k2.x * q2.x + k2.y * q2.y + k3.x * q3.x + k3.y * q3.y;
        p += __shfl_xor_sync(FULL, p, 1);
        p += __shfl_xor_sync(FULL, p, 2);

        float sc = __expf(fminf(fmaxf(p * inv, -5.0f), 5.0f));
        z += sc;

        float2 v0 = __half22float2(*(const __half2*)&vr.x);
        float2 v1 = __half22float2(*(const __half2*)&vr.y);
        float2 v2 = __half22float2(*(const __half2*)&vr.z);
        float2 v3 = __half22float2(*(const __half2*)&vr.w);

        acca.x += sc * v0.x; acca.y += sc * v0.y;
        acca.z += sc * v1.x; acca.w += sc * v1.y;
        accb.x += sc * v2.x; accb.y += sc * v2.y;
        accb.z += sc * v3.x; accb.w += sc * v3.y;
    }

    const float rz = (z > 0.0f) ? 1.0f / z : 0.0f;
    acca.x *= rz; acca.y *= rz; acca.z *= rz; acca.w *= rz;
    accb.x *= rz; accb.y *= rz; accb.z *= rz; accb.w *= rz;

    float4* o = (float4*)(out + (size_t)node * 256);
    o[2 * lane]     = acca;
    o[2 * lane + 1] = accb;
}

// ---------------------------------------------------------------------------
extern "C" void kernel_launch(void* const* d_in, const int* in_sizes, int n_in,
                              void* d_out, int out_size)
{
    const float* h  = (const float*)d_in[0];
    const float* Wq = (const float*)d_in[1];
    const float* bq = (const float*)d_in[2];
    const float* Wk = (const float*)d_in[3];
    const float* bk = (const float*)d_in[4];
    const float* Wv = (const float*)d_in[5];
    const float* bv = (const float*)d_in[6];
    const int*   src = (const int*)d_in[7];
    const int*   dst = (const int*)d_in[8];
    float* out = (float*)d_out;

    const int N = in_sizes[0] / 256;   // 50000
    const int E = in_sizes[7];         // 800000
    const int nb = (N + SCAN_CHUNK - 1) / SCAN_CHUNK;

    // weight fp16 conversion (tiny)
    conv_w<<<(3 * 16384 + 255) / 256, 256>>>((const float4*)Wq,
                                             (const float4*)Wk,
                                             (const float4*)Wv);

    // CSR build (parallel 3-phase scan)
    hist_kernel<<<(E + 255) / 256, 256>>>(dst, E);
    scan_part  <<<nb, 1024>>>(N);
    scan_top   <<<1, 64>>>(nb, N);
    scan_final <<<(N + 255) / 256, 256>>>(N);
    scatter_kernel<<<(E + 255) / 256, 256>>>(src, dst, E);

    // QKV projections: A-resident fp16 tensor-core GEMM (fp32 h read in-kernel)
    cudaFuncSetAttribute(qkv_gemm, cudaFuncAttributeMaxDynamicSharedMemorySize,
                         GSMEM_BYTES);
    dim3 grid((N + 127) / 128, 2);
    qkv_gemm<<<grid, 256, GSMEM_BYTES>>>(h, bq, bk, bv, N);

    attn_fused<<<(N * 32 + 255) / 256, 256>>>(out, N);
}

// round 17
// speedup vs baseline: 2.4066x; 1.0538x over previous
#include <cuda_runtime.h>
#include <cuda_fp16.h>
#include <cstdint>
#include <cstddef>

#define NNODES   50000
#define EDGESMAX 800000
#define HDIM     256   // NUM_HEADS * OUT_DIM
#define SCAN_CHUNK 1024
#define NB_SCAN  ((NNODES + SCAN_CHUNK - 1) / SCAN_CHUNK)   // 49

// -------- scratch (static __device__ arrays; no allocation allowed) --------
__device__ __half2 g_Qh[(size_t)NNODES * 128];   // Q rows, fp16x2 packed
__device__ __half2 g_Kh[(size_t)NNODES * 128];   // K rows, fp16x2 packed
__device__ __half2 g_Vh[(size_t)NNODES * 128];   // V rows, fp16x2 packed
__device__ __half  g_wH[(size_t)3 * HDIM * 256]; // Wq|Wk|Wv converted to fp16
__device__ int   g_deg[NNODES];        // zero-init at load; scan_final re-zeroes
__device__ int   g_cursor[NNODES];
__device__ int   g_rowptr[NNODES + 1];
__device__ int   g_csr_src[EDGESMAX];
__device__ int   g_bsum[NB_SCAN];

__device__ __forceinline__ void cp_async16(uint32_t saddr, const void* gptr) {
    asm volatile("cp.async.cg.shared.global [%0], [%1], 16;"
                 :: "r"(saddr), "l"(gptr));
}

// ---------------------------------------------------------------------------
// K1 (fat): weight fp16 conversion + degree histogram (independent halves)
// ---------------------------------------------------------------------------
__global__ void conv_hist(const float4* __restrict__ Wq4,
                          const float4* __restrict__ Wk4,
                          const float4* __restrict__ Wv4,
                          const int* __restrict__ dst, int E, int nConv) {
    if ((int)blockIdx.x < nConv) {
        int i = blockIdx.x * blockDim.x + threadIdx.x;   // 0 .. 3*16384-1
        if (i < 3 * 16384) {
            int m = i >> 14, r = i & 16383;
            const float4* W4 = (m == 0) ? Wq4 : (m == 1) ? Wk4 : Wv4;
            float4 v = W4[r];
            __half2* o = (__half2*)(g_wH + (size_t)m * 65536);
            o[2 * r]     = __float22half2_rn(make_float2(v.x, v.y));
            o[2 * r + 1] = __float22half2_rn(make_float2(v.z, v.w));
        }
    } else {
        int e = (blockIdx.x - nConv) * blockDim.x + threadIdx.x;
        if (e < E) atomicAdd(&g_deg[dst[e]], 1);
    }
}

// ---------------------------------------------------------------------------
// K2: per-block exclusive scan of 1024-chunks; block totals to g_bsum
// ---------------------------------------------------------------------------
__global__ __launch_bounds__(1024) void scan_part(int n) {
    __shared__ int warp_sums[32];
    const int tid  = threadIdx.x;
    const int lane = tid & 31;
    const int wid  = tid >> 5;
    const int i = blockIdx.x * SCAN_CHUNK + tid;

    int v = (i < n) ? g_deg[i] : 0;
    int x = v;
    #pragma unroll
    for (int off = 1; off < 32; off <<= 1) {
        int t = __shfl_up_sync(0xffffffffu, x, off);
        if (lane >= off) x += t;
    }
    if (lane == 31) warp_sums[wid] = x;
    __syncthreads();
    if (wid == 0) {
        int w = warp_sums[lane];
        #pragma unroll
        for (int off = 1; off < 32; off <<= 1) {
            int t = __shfl_up_sync(0xffffffffu, w, off);
            if (lane >= off) w += t;
        }
        warp_sums[lane] = w;
    }
    __syncthreads();
    int warp_off = (wid > 0) ? warp_sums[wid - 1] : 0;
    if (i < n) g_rowptr[i] = x + warp_off - v;
    if (tid == 1023) g_bsum[blockIdx.x] = x + warp_off;
}

// ---------------------------------------------------------------------------
// K3: scan_final with INLINE top-scan (all shuffles executed convergently).
// ---------------------------------------------------------------------------
__global__ void scan_final(int n, int nb) {
    __shared__ int s_boff[64];
    const int tid = threadIdx.x;

    if (tid < 32) {                                  // warp 0, fully active
        const unsigned FULL = 0xffffffffu;
        int v0 = (tid < nb)      ? g_bsum[tid]      : 0;
        int v1 = (tid + 32 < nb) ? g_bsum[tid + 32] : 0;
        int x0 = v0, x1 = v1;
        #pragma unroll
        for (int off = 1; off < 32; off <<= 1) {
            int t0 = __shfl_up_sync(FULL, x0, off);
            int t1 = __shfl_up_sync(FULL, x1, off);
            if ((tid & 31) >= off) { x0 += t0; x1 += t1; }
        }
        int tot0 = __shfl_sync(FULL, x0, 31);        // all 32 lanes participate
        int tot1 = __shfl_sync(FULL, x1, 31);        // all 32 lanes participate
        s_boff[tid]      = x0 - v0;                  // exclusive
        s_boff[tid + 32] = tot0 + x1 - v1;
        if (tid == 31 && blockIdx.x == 0)
            g_rowptr[n] = tot0 + tot1;               // register use only
    }
    __syncthreads();

    int i = blockIdx.x * blockDim.x + tid;
    if (i < n) {
        int r = g_rowptr[i] + s_boff[i >> 10];
        g_rowptr[i] = r;
        g_cursor[i] = r;
        g_deg[i]    = 0;
    }
}

// ---------------------------------------------------------------------------
// K4 (fat): A-resident fused QKV GEMM  +  grid-stride CSR scatter.
// blocks [0, nGemm): GEMM (bm = b>>1, ncol0 = (b&1)*128)
// blocks [nGemm, nGemm+NSCAT_BLK): scatter (independent of GEMM)
// ---------------------------------------------------------------------------
#define A_STRIDE_U32 132                 // 128 data u32 + 4 pad (528 B/row)
#define A_U32        (128 * A_STRIDE_U32)
#define B_STRIDE_U32 20                  // 16 data u32 + 4 pad (80 B/row)
#define B_U32        (128 * B_STRIDE_U32)
#define GSMEM_BYTES  ((A_U32 + 4 * B_U32) * 4)   // 108544 B
#define NSCAT_BLK    1024

__global__ __launch_bounds__(256, 2) void gemm_scatter(
    const float* __restrict__ h,
    const float* __restrict__ bq, const float* __restrict__ bk,
    const float* __restrict__ bv, int Nrows,
    const int* __restrict__ src, const int* __restrict__ dst, int E,
    int nGemm)
{
    // ---------------- scatter path ----------------
    if ((int)blockIdx.x >= nGemm) {
        int base = (blockIdx.x - nGemm) * blockDim.x + threadIdx.x;
        for (int e = base; e < E; e += NSCAT_BLK * 256) {
            int pos = atomicAdd(&g_cursor[dst[e]], 1);
            g_csr_src[pos] = src[e];
        }
        return;
    }

    // ---------------- GEMM path ----------------
    extern __shared__ uint32_t sm[];     // [A | B0 | B1 | B2 | B3]

    const int tid  = threadIdx.x;
    const int lane = tid & 31;
    const int warp = tid >> 5;
    const int wm = warp >> 2;            // 0..1
    const int wn = warp & 3;             // 0..3
    const int bm = blockIdx.x >> 1;
    const int ncol0 = (blockIdx.x & 1) * 128;

    const uint32_t smem_base  = (uint32_t)__cvta_generic_to_shared(sm);
    const uint32_t smem_Bbase = smem_base + A_U32 * 4;

    auto load_B = [&](int g, int buf) {
        int w = g >> 3, it = g & 7;
        const __half* Wp = g_wH + (size_t)w * 65536;
        #pragma unroll
        for (int i = 0; i < 2; i++) {
            int c = tid + i * 256;           // 0..511 chunks of 16B
            int r = c >> 2, chk = c & 3;
            const __half* gp = Wp + (size_t)(ncol0 + r) * 256 + it * 32 + chk * 8;
            uint32_t sa = smem_Bbase + (uint32_t)(buf * B_U32 * 4 + r * B_STRIDE_U32 * 4 + chk * 16);
            cp_async16(sa, gp);
        }
        asm volatile("cp.async.commit_group;" ::: "memory");
    };

    load_B(0, 0);
    load_B(1, 1);
    load_B(2, 2);

    // ---- load + convert full A tile from fp32 h (once per CTA) ----
    {
        uint32_t* As = sm;
        #pragma unroll
        for (int i = 0; i < 32; i++) {
            int c = tid + i * 256;           // 0..8191 float4 chunks
            int r = c >> 6, f4 = c & 63;
            int grow = bm * 128 + r;
            float4 v = (grow < Nrows)
                     ? ((const float4*)h)[(size_t)grow * 64 + f4]
                     : make_float4(0.f, 0.f, 0.f, 0.f);
            __half2 h0 = __float22half2_rn(make_float2(v.x, v.y));
            __half2 h1 = __float22half2_rn(make_float2(v.z, v.w));
            uint32_t* s = As + r * A_STRIDE_U32 + f4 * 2;
            s[0] = *(uint32_t*)&h0;
            s[1] = *(uint32_t*)&h1;
        }
    }

    uint32_t aAddr[4];
    #pragma unroll
    for (int mt = 0; mt < 4; mt++) {
        int rowA = wm * 64 + mt * 16 + (lane & 7) + ((lane >> 3) & 1) * 8;
        aAddr[mt] = smem_base + (uint32_t)(rowA * A_STRIDE_U32 * 4 + ((lane >> 4) * 8) * 2);
    }
    uint32_t bAddrBase[4];
    #pragma unroll
    for (int nt = 0; nt < 4; nt++) {
        int rowB = wn * 32 + nt * 8 + (lane & 7);
        bAddrBase[nt] = (uint32_t)(rowB * B_STRIDE_U32 * 4 + (((lane >> 3) & 1) * 8) * 2);
    }

    float acc[4][4][4];

    for (int g = 0; g < 24; g++) {
        if (g <= 21)      asm volatile("cp.async.wait_group 2;" ::: "memory");
        else if (g == 22) asm volatile("cp.async.wait_group 1;" ::: "memory");
        else              asm volatile("cp.async.wait_group 0;" ::: "memory");
        __syncthreads();   // B[g] visible; compute of g-1 done -> buf (g-1)&3 free

        if ((g & 7) == 0) {
            #pragma unroll
            for (int i = 0; i < 4; i++)
                #pragma unroll
                for (int j = 0; j < 4; j++)
                    #pragma unroll
                    for (int k = 0; k < 4; k++) acc[i][j][k] = 0.0f;
        }

        if (g + 3 < 24) load_B(g + 3, (g + 3) & 3);

        const int it = g & 7;
        const uint32_t bStage = smem_Bbase + (uint32_t)((g & 3) * B_U32 * 4);

        #pragma unroll
        for (int ks = 0; ks < 2; ks++) {
            const int kOffA = (it * 32 + ks * 16) * 2;   // bytes
            const int kOffB = (ks * 16) * 2;
            uint32_t a[4][4], b[4][2];
            #pragma unroll
            for (int mt = 0; mt < 4; mt++)
                asm volatile(
                    "ldmatrix.sync.aligned.m8n8.x4.shared.b16 {%0,%1,%2,%3}, [%4];"
                    : "=r"(a[mt][0]), "=r"(a[mt][1]), "=r"(a[mt][2]), "=r"(a[mt][3])
                    : "r"(aAddr[mt] + kOffA));
            #pragma unroll
            for (int nt = 0; nt < 4; nt++)
                asm volatile(
                    "ldmatrix.sync.aligned.m8n8.x2.shared.b16 {%0,%1}, [%2];"
                    : "=r"(b[nt][0]), "=r"(b[nt][1])
                    : "r"(bStage + bAddrBase[nt] + kOffB));
            #pragma unroll
            for (int mt = 0; mt < 4; mt++)
                #pragma unroll
                for (int nt = 0; nt < 4; nt++)
                    asm volatile(
                        "mma.sync.aligned.m16n8k16.row.col.f32.f16.f16.f32 "
                        "{%0,%1,%2,%3}, {%4,%5,%6,%7}, {%8,%9}, {%0,%1,%2,%3};"
                        : "+f"(acc[mt][nt][0]), "+f"(acc[mt][nt][1]),
                          "+f"(acc[mt][nt][2]), "+f"(acc[mt][nt][3])
                        : "r"(a[mt][0]), "r"(a[mt][1]), "r"(a[mt][2]), "r"(a[mt][3]),
                          "r"(b[nt][0]), "r"(b[nt][1]));
        }

        if (it == 7) {
            const int w = g >> 3;
            const float* bias = (w == 0) ? bq : (w == 1) ? bk : bv;
            __half2* targetH  = (w == 0) ? g_Qh : (w == 1) ? g_Kh : g_Vh;
            #pragma unroll
            for (int mt = 0; mt < 4; mt++) {
                int r0 = wm * 64 + mt * 16 + (lane >> 2);
                #pragma unroll
                for (int nt = 0; nt < 4; nt++) {
                    int c0 = wn * 32 + nt * 8 + (lane & 3) * 2;
                    int j = ncol0 + c0;
                    float b0 = bias[j], b1 = bias[j + 1];
                    int grow0 = bm * 128 + r0;
                    if (grow0 < Nrows)
                        targetH[(size_t)grow0 * 128 + (j >> 1)] =
                            __float22half2_rn(make_float2(acc[mt][nt][0] + b0,
                                                          acc[mt][nt][1] + b1));
                    int grow1 = grow0 + 8;
                    if (grow1 < Nrows)
                        targetH[(size_t)grow1 * 128 + (j >> 1)] =
                            __float22half2_rn(make_float2(acc[mt][nt][2] + b0,
                                                          acc[mt][nt][3] + b1));
                }
            }
        }
    }
}

// ---------------------------------------------------------------------------
// K5: single-pass fused attention, all-fp16 gather.
// ---------------------------------------------------------------------------
__global__ __launch_bounds__(256) void attn_fused(
    float* __restrict__ out, int n_nodes)
{
    const int node = (blockIdx.x * blockDim.x + threadIdx.x) >> 5;
    if (node >= n_nodes) return;
    const int lane = threadIdx.x & 31;
    const unsigned FULL = 0xffffffffu;
    const float inv = 0.17677669529663687f;   // 1/sqrt(32)

    const int beg = g_rowptr[node];
    const int end = g_rowptr[node + 1];

    uint4 qr = ((const uint4*)(g_Qh + (size_t)node * 128))[lane];
    float2 q0 = __half22float2(*(const __half2*)&qr.x);
    float2 q1 = __half22float2(*(const __half2*)&qr.y);
    float2 q2 = __half22float2(*(const __half2*)&qr.z);
    float2 q3 = __half22float2(*(const __half2*)&qr.w);

    float4 acca = make_float4(0.f, 0.f, 0.f, 0.f);
    float4 accb = make_float4(0.f, 0.f, 0.f, 0.f);
    float z = 0.0f;

    for (int i = beg; i < end; i++) {
        const int s = g_csr_src[i];
        uint4 kr = ((const uint4*)(g_Kh + (size_t)s * 128))[lane];
        uint4 vr = ((const uint4*)(g_Vh + (size_t)s * 128))[lane];

        float2 k0 = __half22float2(*(const __half2*)&kr.x);
        float2 k1 = __half22float2(*(const __half2*)&kr.y);
        float2 k2 = __half22float2(*(const __half2*)&kr.z);
        float2 k3 = __half22float2(*(const __half2*)&kr.w);

        float p = k0.x * q0.x + k0.y * q0.y + k1.x * q1.x + k1.y * q1.y
                + k2.x * q2.x + k2.y * q2.y + k3.x * q3.x + k3.y * q3.y;
        p += __shfl_xor_sync(FULL, p, 1);
        p += __shfl_xor_sync(FULL, p, 2);

        float sc = __expf(fminf(fmaxf(p * inv, -5.0f), 5.0f));
        z += sc;

        float2 v0 = __half22float2(*(const __half2*)&vr.x);
        float2 v1 = __half22float2(*(const __half2*)&vr.y);
        float2 v2 = __half22float2(*(const __half2*)&vr.z);
        float2 v3 = __half22float2(*(const __half2*)&vr.w);

        acca.x += sc * v0.x; acca.y += sc * v0.y;
        acca.z += sc * v1.x; acca.w += sc * v1.y;
        accb.x += sc * v2.x; accb.y += sc * v2.y;
        accb.z += sc * v3.x; accb.w += sc * v3.y;
    }

    const float rz = (z > 0.0f) ? 1.0f / z : 0.0f;
    acca.x *= rz; acca.y *= rz; acca.z *= rz; acca.w *= rz;
    accb.x *= rz; accb.y *= rz; accb.z *= rz; accb.w *= rz;

    float4* o = (float4*)(out + (size_t)node * 256);
    o[2 * lane]     = acca;
    o[2 * lane + 1] = accb;
}

// ---------------------------------------------------------------------------
extern "C" void kernel_launch(void* const* d_in, const int* in_sizes, int n_in,
                              void* d_out, int out_size)
{
    const float* h  = (const float*)d_in[0];
    const float* Wq = (const float*)d_in[1];
    const float* bq = (const float*)d_in[2];
    const float* Wk = (const float*)d_in[3];
    const float* bk = (const float*)d_in[4];
    const float* Wv = (const float*)d_in[5];
    const float* bv = (const float*)d_in[6];
    const int*   src = (const int*)d_in[7];
    const int*   dst = (const int*)d_in[8];
    float* out = (float*)d_out;

    const int N = in_sizes[0] / 256;   // 50000
    const int E = in_sizes[7];         // 800000
    const int nb = (N + SCAN_CHUNK - 1) / SCAN_CHUNK;   // 49

    // K1: weight conversion + histogram (merged)
    const int nConv = (3 * 16384 + 255) / 256;          // 192
    const int nHist = (E + 255) / 256;                  // 3125
    conv_hist<<<nConv + nHist, 256>>>((const float4*)Wq, (const float4*)Wk,
                                      (const float4*)Wv, dst, E, nConv);

    // K2/K3: scan
    scan_part <<<nb, 1024>>>(N);
    scan_final<<<(N + 255) / 256, 256>>>(N, nb);

    // K4: GEMM + scatter (merged, independent halves)
    const int nGemm = ((N + 127) / 128) * 2;            // 782
    cudaFuncSetAttribute(gemm_scatter, cudaFuncAttributeMaxDynamicSharedMemorySize,
                         GSMEM_BYTES);
    gemm_scatter<<<nGemm + NSCAT_BLK, 256, GSMEM_BYTES>>>(
        h, bq, bk, bv, N, src, dst, E, nGemm);

    // K5: fused attention
    attn_fused<<<(N * 32 + 255) / 256, 256>>>(out, N);
}